// round 14
// baseline (speedup 1.0000x reference)
#include <cuda_runtime.h>
#include <cuda_fp16.h>
#include <math.h>
#include <stdint.h>

#define Cn 512
#define Bn 64
#define Nn 1024
#define Mn 16
#define SCALE 0.04419417382415922f   // 512^-0.5

// ---------------- scratch (allocation-free) ----------------
__device__ float g_xp  [1024 * 512];
__device__ float g_bqA [1024];
__device__ float g_bvo [512];
__device__ float g_v   [512];           // Wq^T bq
__device__ float g_WqT [512 * 512];
__device__ float g_WvT [512 * 512];
__device__ float g_WoT [512 * 512];
__device__ float g_WcT [512 * 512];
__device__ float g_L2  [64 * 16 * 1024];
__device__ float g_L1  [64 * 1024 * 16];
__device__ float g_xa  [1024 * 512];
__device__ float g_AFo [1024 * 512];
__device__ __half g_xh   [(size_t)64 * 1024 * 512];
__device__ __half g_xl   [(size_t)64 * 1024 * 512];
__device__ __half g_aqkh [64 * 32 * 512];
__device__ __half g_aqkl [64 * 32 * 512];
__device__ __half g_WqTh [512 * 512];
__device__ __half g_WqTl [512 * 512];
__device__ __half g_WkTh [512 * 512];
__device__ __half g_WkTl [512 * 512];
__device__ __half g_Ah   [1024 * 512];
__device__ __half g_Al   [1024 * 512];

__device__ __forceinline__ uint32_t smem_u32(const void* p) {
    return (uint32_t)__cvta_generic_to_shared(p);
}
__device__ __forceinline__ void cp_async16(uint32_t s, const void* g) {
    asm volatile("cp.async.cg.shared.global [%0], [%1], 16;" :: "r"(s), "l"(g));
}
__device__ __forceinline__ void ldx4(uint32_t* r, uint32_t addr) {
    asm volatile("ldmatrix.sync.aligned.m8n8.x4.shared.b16 {%0,%1,%2,%3}, [%4];"
                 : "=r"(r[0]), "=r"(r[1]), "=r"(r[2]), "=r"(r[3]) : "r"(addr));
}
__device__ __forceinline__ void ldx2t(uint32_t* r, uint32_t addr) {
    asm volatile("ldmatrix.sync.aligned.m8n8.x2.trans.shared.b16 {%0,%1}, [%2];"
                 : "=r"(r[0]), "=r"(r[1]) : "r"(addr));
}
__device__ __forceinline__ void mma16816(float* c, const uint32_t* a, uint32_t b0, uint32_t b1) {
    asm volatile(
        "mma.sync.aligned.m16n8k16.row.col.f32.f16.f16.f32 "
        "{%0,%1,%2,%3}, {%4,%5,%6,%7}, {%8,%9}, {%0,%1,%2,%3};"
        : "+f"(c[0]), "+f"(c[1]), "+f"(c[2]), "+f"(c[3])
        : "r"(a[0]), "r"(a[1]), "r"(a[2]), "r"(a[3]), "r"(b0), "r"(b1));
}

// ================= prep: transposes (+fp16), v, bvo =================
// z 0: Wq -> WqT fp32 + fp16 h/l ; z 1: Wv -> WvT ; z 2: Wo -> WoT ;
// z 3: vector work (bvo ids 0..63, v ids 64..65) ; z 4: Wk -> WkT fp16 h/l only.
__global__ void prep_kernel(const float* __restrict__ Wq, const float* __restrict__ Wk,
                            const float* __restrict__ Wv, const float* __restrict__ Wo,
                            const float* __restrict__ bq, const float* __restrict__ bv,
                            float* __restrict__ WqT, float* __restrict__ WvT,
                            float* __restrict__ WoT, __half* __restrict__ WqTh,
                            __half* __restrict__ WqTl, __half* __restrict__ WkTh,
                            __half* __restrict__ WkTl, float* __restrict__ v,
                            float* __restrict__ bvo)
{
    const int z = blockIdx.z;
    if (z == 3) {
        const int id  = blockIdx.y * 16 + blockIdx.x;
        const int tid = threadIdx.y * 32 + threadIdx.x;
        if (id < 64) {
            // bvo[r] = Wo[r,:] . bv
            const int row  = id * 8 + (tid >> 5);
            const int lane = tid & 31;
            const float* sr = Wo + (size_t)row * Cn;
            float s = 0.f;
#pragma unroll
            for (int k = 0; k < 16; k++) s += sr[lane + 32 * k] * __ldg(&bv[lane + 32 * k]);
#pragma unroll
            for (int off = 16; off > 0; off >>= 1) s += __shfl_xor_sync(0xffffffffu, s, off);
            if (lane == 0) bvo[row] = s;
        } else if (id < 66) {
            // v[n] = sum_c Wq[c,n] * bq[c]
            const int n = (id - 64) * 256 + tid;
            float s = 0.f;
#pragma unroll 8
            for (int c = 0; c < Cn; c++) s = fmaf(__ldg(&Wq[(size_t)c * Cn + n]), __ldg(&bq[c]), s);
            v[n] = s;
        }
        return;
    }
    __shared__ float t[32][33];
    const float* s;
    if (z == 0)      s = Wq;
    else if (z == 1) s = Wv;
    else if (z == 2) s = Wo;
    else             s = Wk;   // z == 4
    const int x  = blockIdx.x * 32 + threadIdx.x;
    const int y0 = blockIdx.y * 32 + threadIdx.y;
#pragma unroll
    for (int j = 0; j < 32; j += 8)
        t[threadIdx.y + j][threadIdx.x] = s[(size_t)(y0 + j) * Cn + x];
    __syncthreads();
    const int ox  = blockIdx.y * 32 + threadIdx.x;
    const int oy0 = blockIdx.x * 32 + threadIdx.y;
#pragma unroll
    for (int j = 0; j < 32; j += 8) {
        const float val = t[threadIdx.x][threadIdx.y + j];
        const size_t di = (size_t)(oy0 + j) * Cn + ox;
        if (z == 0) {
            WqT[di] = val;
            __half h = __float2half(val);
            WqTh[di] = h;
            WqTl[di] = __float2half(val - __half2float(h));
        } else if (z == 1) WvT[di] = val;
        else if (z == 2)   WoT[di] = val;
        else {             // z == 4
            __half h = __float2half(val);
            WkTh[di] = h;
            WkTl[di] = __float2half(val - __half2float(h));
        }
    }
}

// ================= split x -> fp16 hi/lo + pooled xp + bqA = xp.v =================
__global__ __launch_bounds__(512)
void split_pool_kernel(const float* __restrict__ x, const float* __restrict__ v,
                       __half* __restrict__ xh, __half* __restrict__ xl,
                       float* __restrict__ xp, float* __restrict__ bqA)
{
    __shared__ float red[512];
    const int bm = blockIdx.x;
    const int c  = threadIdx.x;
    const size_t ob = (size_t)bm * 64 * Cn + c;
    const float* base = x + ob;
    float s = 0.f;
#pragma unroll 4
    for (int t = 0; t < 64; t++) {
        float vv = base[(size_t)t * Cn];
        s += vv;
        __half h = __float2half(vv);
        xh[ob + (size_t)t * Cn] = h;
        xl[ob + (size_t)t * Cn] = __float2half(vv - __half2float(h));
    }
    const float xv = s * (1.0f / 64.0f);
    xp[(size_t)bm * Cn + c] = xv;

    red[c] = xv * __ldg(&v[c]);
    __syncthreads();
    for (int st = 256; st > 32; st >>= 1) {
        if (c < st) red[c] += red[c + st];
        __syncthreads();
    }
    if (c < 32) {
        float r = red[c] + red[c + 32];
#pragma unroll
        for (int off = 16; off > 0; off >>= 1) r += __shfl_xor_sync(0xffffffffu, r, off);
        if (c == 0) bqA[bm] = r;
    }
}

// ================= fp32 GEMM machinery (as R13) =================
#define XS_FLOATS (64 * 36)
#define WS_FLOATS (32 * 68)
#define STAGE_FLOATS (XS_FLOATS + WS_FLOATS)
#define GEMM_SMEM (3 * STAGE_FLOATS * 4)

#define GEMM_PROLOGUE(Xp, Wp, R0, N0)                                           \
    const int tid = threadIdx.x;                                                \
    const int tx = tid & 15, ty = tid >> 4;                                     \
    const int xlr = tid >> 2, xlk = (tid & 3) * 8;                              \
    const int wwk = tid >> 3, wwn = (tid & 7) * 8;                              \
    const float* gX = (Xp) + (size_t)((R0) + xlr) * Cn + xlk;                   \
    const float* gW = (Wp) + (size_t)wwk * Cn + (N0) + wwn;                     \
    const uint32_t sbase = smem_u32(sm);                                        \
    const uint32_t xdst = sbase + (uint32_t)(xlr * 36 + xlk) * 4u;              \
    const uint32_t wdst = sbase + (uint32_t)(XS_FLOATS + wwk * 68 + wwn) * 4u;

#define G_LOAD(ST, K0)                                                          \
    do {                                                                        \
        const uint32_t so_ = (uint32_t)(ST) * (STAGE_FLOATS * 4u);              \
        cp_async16(xdst + so_,      gX + (K0));                                 \
        cp_async16(xdst + so_ + 16, gX + (K0) + 4);                             \
        cp_async16(wdst + so_,      gW + (size_t)(K0) * Cn);                    \
        cp_async16(wdst + so_ + 16, gW + (size_t)(K0) * Cn + 4);                \
        asm volatile("cp.async.commit_group;" ::: "memory");                    \
    } while (0)

#define GEMM_MAINLOOP(acc)                                                      \
    G_LOAD(0, 0);                                                               \
    G_LOAD(1, 32);                                                              \
    _Pragma("unroll 1")                                                         \
    for (int it = 0; it < 16; it++) {                                           \
        if (it < 15) asm volatile("cp.async.wait_group 1;" ::: "memory");       \
        else         asm volatile("cp.async.wait_group 0;" ::: "memory");       \
        __syncthreads();                                                        \
        if (it + 2 < 16) G_LOAD((it + 2) % 3, (it + 2) * 32);                   \
        const float* Xst = sm + (it % 3) * STAGE_FLOATS;                        \
        const float* Wst = Xst + XS_FLOATS;                                     \
        _Pragma("unroll")                                                       \
        for (int k4 = 0; k4 < 8; k4++) {                                        \
            float aa[4][4], bb[4][4];                                           \
            _Pragma("unroll")                                                   \
            for (int i = 0; i < 4; i++) {                                       \
                float4 a = *(const float4*)(Xst + (ty * 4 + i) * 36 + k4 * 4);  \
                aa[i][0] = a.x; aa[i][1] = a.y; aa[i][2] = a.z; aa[i][3] = a.w; \
            }                                                                   \
            _Pragma("unroll")                                                   \
            for (int q = 0; q < 4; q++) {                                       \
                float4 b = *(const float4*)(Wst + (k4 * 4 + q) * 68 + tx * 4);  \
                bb[q][0] = b.x; bb[q][1] = b.y; bb[q][2] = b.z; bb[q][3] = b.w; \
            }                                                                   \
            _Pragma("unroll")                                                   \
            for (int i = 0; i < 4; i++)                                         \
                _Pragma("unroll")                                               \
                for (int j = 0; j < 4; j++)                                     \
                    _Pragma("unroll")                                           \
                    for (int q = 0; q < 4; q++)                                 \
                        acc[i][j] = fmaf(aa[i][q], bb[q][j], acc[i][j]);        \
        }                                                                       \
    }

// ================= gemm_nn (fp32 out; used for AFo) =================
__global__ __launch_bounds__(256)
void gemm_nn(const float* __restrict__ X, const float* __restrict__ W0,
             const float* __restrict__ W1, const float* __restrict__ bias,
             float* __restrict__ Y0, float* __restrict__ Y1, int nsplit)
{
    extern __shared__ float sm[];
    const float* W; float* Y; int n0;
    if ((int)blockIdx.x < nsplit) { W = W0; Y = Y0; n0 = blockIdx.x * 64; }
    else                          { W = W1; Y = Y1; n0 = (blockIdx.x - nsplit) * 64; }
    const int r0 = blockIdx.y * 64;
    GEMM_PROLOGUE(X, W, r0, n0);

    float acc[4][4];
#pragma unroll
    for (int i = 0; i < 4; i++)
#pragma unroll
        for (int j = 0; j < 4; j++) acc[i][j] = 0.f;

    GEMM_MAINLOOP(acc);

    float4 bi = make_float4(0.f, 0.f, 0.f, 0.f);
    if (bias) bi = *(const float4*)(bias + n0 + tx * 4);
#pragma unroll
    for (int i = 0; i < 4; i++) {
        float4 o;
        o.x = acc[i][0] + bi.x; o.y = acc[i][1] + bi.y;
        o.z = acc[i][2] + bi.z; o.w = acc[i][3] + bi.w;
        *(float4*)(Y + (size_t)(r0 + ty * 4 + i) * Cn + n0 + tx * 4) = o;
    }
}

// ================= gemm_awc: A (fp16 h/l out) 128 blk + WcT (fp32) 64 blk =================
__global__ __launch_bounds__(256)
void gemm_awc(const float* __restrict__ xp, const float* __restrict__ WqT,
              const float* __restrict__ bq, __half* __restrict__ Ah,
              __half* __restrict__ Al, const float* __restrict__ WvT,
              const float* __restrict__ WoT, float* __restrict__ WcT)
{
    extern __shared__ float sm[];
    const int isA = (int)blockIdx.x < 128;
    const float *X, *W; int r0, n0;
    if (isA) {
        const int l = blockIdx.x;
        X = xp; W = WqT;
        n0 = (l & 7) * 64; r0 = (l >> 3) * 64;
    } else {
        const int l = blockIdx.x - 128;
        X = WvT; W = WoT;
        n0 = (l & 7) * 64; r0 = (l >> 3) * 64;
    }
    GEMM_PROLOGUE(X, W, r0, n0);

    float acc[4][4];
#pragma unroll
    for (int i = 0; i < 4; i++)
#pragma unroll
        for (int j = 0; j < 4; j++) acc[i][j] = 0.f;

    GEMM_MAINLOOP(acc);

    if (isA) {
        float4 bi = *(const float4*)(bq + n0 + tx * 4);
#pragma unroll
        for (int i = 0; i < 4; i++) {
            float o0 = acc[i][0] + bi.x, o1 = acc[i][1] + bi.y;
            float o2 = acc[i][2] + bi.z, o3 = acc[i][3] + bi.w;
            const size_t dst = (size_t)(r0 + ty * 4 + i) * Cn + n0 + tx * 4;
            __half h0 = __float2half(o0), h1 = __float2half(o1);
            __half h2 = __float2half(o2), h3 = __float2half(o3);
            *(__half2*)(Ah + dst)     = __halves2half2(h0, h1);
            *(__half2*)(Ah + dst + 2) = __halves2half2(h2, h3);
            *(__half2*)(Al + dst)     = __halves2half2(__float2half(o0 - __half2float(h0)),
                                                       __float2half(o1 - __half2float(h1)));
            *(__half2*)(Al + dst + 2) = __halves2half2(__float2half(o2 - __half2float(h2)),
                                                       __float2half(o3 - __half2float(h3)));
        }
    } else {
#pragma unroll
        for (int i = 0; i < 4; i++) {
            float4 o;
            o.x = acc[i][0]; o.y = acc[i][1]; o.z = acc[i][2]; o.w = acc[i][3];
            *(float4*)(WcT + (size_t)(r0 + ty * 4 + i) * Cn + n0 + tx * 4) = o;
        }
    }
}

// ================= gemm_aqk_mma: Aq|Ak via fp16 mma, 3-term =================
// grid (16, 8): bx<8 -> Wq (joff 0, B=WqTh/l), bx>=8 -> Wk (joff 16, B=WkTh/l).
// block: 128 A-rows x 64 output cols, K=512 in 8 chunks of 64, 2-stage.
#define AQ_STAGE 49152       // Ah 16K + Al 16K + Bh 8K + Bl 8K
#define AQ_SMEM (2 * AQ_STAGE)

__global__ __launch_bounds__(256)
void gemm_aqk_mma(const __half* __restrict__ Ahg, const __half* __restrict__ Alg,
                  const __half* __restrict__ Wqh, const __half* __restrict__ Wql,
                  const __half* __restrict__ Wkh, const __half* __restrict__ Wkl,
                  __half* __restrict__ Oh, __half* __restrict__ Ol)
{
    extern __shared__ char smem[];
    const uint32_t sbase = smem_u32(smem);
    const int isK = (int)blockIdx.x >= 8;
    const __half* Bh_g = isK ? Wkh : Wqh;
    const __half* Bl_g = isK ? Wkl : Wql;
    const int n0 = ((int)blockIdx.x & 7) * 64;
    const int rowblk = blockIdx.y * 128;
    const int t = threadIdx.x;
    const int L = t & 31;
    const int w = t >> 5;

#define AQ_LOAD(I)                                                                        \
    do {                                                                                  \
        const int s_ = (I) & 1; const int k0_ = (I) * 64;                                 \
        const uint32_t sb_ = sbase + s_ * AQ_STAGE;                                       \
        {                                                                                 \
            const int row = t >> 1; const int cb = (t & 1) * 4;                           \
            const __half* gh = Ahg + (size_t)(rowblk + row) * Cn + k0_ + cb * 8;          \
            const __half* gl = Alg + (size_t)(rowblk + row) * Cn + k0_ + cb * 8;          \
            _Pragma("unroll")                                                             \
            for (int j = 0; j < 4; j++) {                                                 \
                uint32_t o = (uint32_t)(row * 128 + (cb + j) * 16) ^ ((uint32_t)(row & 7) << 4); \
                cp_async16(sb_ + o, gh + j * 8);                                          \
                cp_async16(sb_ + 16384 + o, gl + j * 8);                                  \
            }                                                                             \
        }                                                                                 \
        {                                                                                 \
            const int jr = t >> 2; const int ch = (t & 3) * 2;                            \
            const __half* gh = Bh_g + (size_t)(n0 + jr) * Cn + k0_ + ch * 8;              \
            const __half* gl = Bl_g + (size_t)(n0 + jr) * Cn + k0_ + ch * 8;              \
            _Pragma("unroll")                                                             \
            for (int j = 0; j < 2; j++) {                                                 \
                uint32_t o = (uint32_t)(jr * 128 + (ch + j) * 16) ^ ((uint32_t)(jr & 7) << 4); \
                cp_async16(sb_ + 32768 + o, gh + j * 8);                                  \
                cp_async16(sb_ + 40960 + o, gl + j * 8);                                  \
            }                                                                             \
        }                                                                                 \
        asm volatile("cp.async.commit_group;" ::: "memory");                              \
    } while (0)

    float acc[8][4];
#pragma unroll
    for (int i = 0; i < 8; i++)
#pragma unroll
        for (int j = 0; j < 4; j++) acc[i][j] = 0.f;

    AQ_LOAD(0);
    AQ_LOAD(1);

    const int a_row = w * 16 + (L & 15);
    const int a_cx  = ((L >> 4) & 1) * 16;
    const int b_rb  = (L & 7) + ((L >> 4) & 1) * 8;
    const int b_cx  = ((L >> 3) & 1) * 16;

#pragma unroll 1
    for (int kt = 0; kt < 8; kt++) {
        if (kt < 7) asm volatile("cp.async.wait_group 1;" ::: "memory");
        else        asm volatile("cp.async.wait_group 0;" ::: "memory");
        __syncthreads();
        const uint32_t sb_ = sbase + (kt & 1) * AQ_STAGE;
#pragma unroll
        for (int ks = 0; ks < 4; ks++) {
            uint32_t ah[4], al[4];
            uint32_t oa = (uint32_t)(a_row * 128 + ks * 32 + a_cx) ^ ((uint32_t)(a_row & 7) << 4);
            ldx4(ah, sb_ + oa);
            ldx4(al, sb_ + 16384 + oa);
            uint32_t bh[4][4], bl[4][4];
#pragma unroll
            for (int p = 0; p < 4; p++) {
                const int rn = b_rb + p * 16;
                uint32_t ob_ = (uint32_t)(rn * 128 + ks * 32 + b_cx) ^ ((uint32_t)(rn & 7) << 4);
                ldx4(bh[p], sb_ + 32768 + ob_);
                ldx4(bl[p], sb_ + 40960 + ob_);
            }
#pragma unroll
            for (int nt = 0; nt < 8; nt++) {
                const int p = nt >> 1, pi = (nt & 1) * 2;
                mma16816(acc[nt], ah, bh[p][pi], bh[p][pi + 1]);
                mma16816(acc[nt], ah, bl[p][pi], bl[p][pi + 1]);
                mma16816(acc[nt], al, bh[p][pi], bh[p][pi + 1]);
            }
        }
        if (kt + 2 < 8) { __syncthreads(); AQ_LOAD(kt + 2); }
    }
#undef AQ_LOAD

    // epilogue: rows r = rowblk + w*16 + g (+8); dst remap to [b][32][512]
    const int g  = L >> 2;
    const int cq = (L & 3) * 2;
    const int joff = isK ? 16 : 0;
    const int r0v = rowblk + w * 16 + g;
    const int r1v = r0v + 8;
    const size_t d0 = ((size_t)(r0v >> 4) * 32 + (r0v & 15) + joff) * Cn + n0;
    const size_t d1 = ((size_t)(r1v >> 4) * 32 + (r1v & 15) + joff) * Cn + n0;
#pragma unroll
    for (int nt = 0; nt < 8; nt++) {
        const int col = nt * 8 + cq;
        __half h0 = __float2half(acc[nt][0]);
        __half h1 = __float2half(acc[nt][1]);
        __half h2 = __float2half(acc[nt][2]);
        __half h3 = __float2half(acc[nt][3]);
        *(__half2*)(Oh + d0 + col) = __halves2half2(h0, h1);
        *(__half2*)(Oh + d1 + col) = __halves2half2(h2, h3);
        *(__half2*)(Ol + d0 + col) = __halves2half2(__float2half(acc[nt][0] - __half2float(h0)),
                                                    __float2half(acc[nt][1] - __half2float(h1)));
        *(__half2*)(Ol + d1 + col) = __halves2half2(__float2half(acc[nt][2] - __half2float(h2)),
                                                    __float2half(acc[nt][3] - __half2float(h3)));
    }
}

// ================= logits via mma (unchanged from R12/13) =================
#define LG_STAGE 40960
#define LG_SMEM (2 * LG_STAGE + 64)

__global__ __launch_bounds__(256)
void logits12_mma(const __half* __restrict__ Xh, const __half* __restrict__ Xl,
                  const __half* __restrict__ Ah_g, const __half* __restrict__ Al_g,
                  const float* __restrict__ bqA,
                  float* __restrict__ L1, float* __restrict__ L2)
{
    extern __shared__ char smem[];
    const uint32_t sbase = smem_u32(smem);
    const int b = blockIdx.y;
    const int tokblk = blockIdx.x * 128;
    const int t = threadIdx.x;
    const int L = t & 31;
    const int w = t >> 5;

    if (t < 16) ((float*)(smem + 2 * LG_STAGE))[t] = bqA[b * 16 + t];

#define LG_LOAD(I)                                                                        \
    do {                                                                                  \
        const int s_ = (I) & 1; const int k0_ = (I) * 64;                                 \
        const uint32_t sb_ = sbase + s_ * LG_STAGE;                                       \
        {                                                                                 \
            const int row = t >> 1; const int cb = (t & 1) * 4;                           \
            const __half* gh = Xh + ((size_t)(b * Nn + tokblk + row)) * Cn + k0_ + cb * 8;\
            const __half* gl = Xl + ((size_t)(b * Nn + tokblk + row)) * Cn + k0_ + cb * 8;\
            _Pragma("unroll")                                                             \
            for (int j = 0; j < 4; j++) {                                                 \
                uint32_t o = (uint32_t)(row * 128 + (cb + j) * 16) ^ ((uint32_t)(row & 7) << 4); \
                cp_async16(sb_ + o, gh + j * 8);                                          \
                cp_async16(sb_ + 16384 + o, gl + j * 8);                                  \
            }                                                                             \
        }                                                                                 \
        {                                                                                 \
            const int jr = t >> 3; const int ch = t & 7;                                  \
            uint32_t o = (uint32_t)(jr * 128 + ch * 16) ^ ((uint32_t)(jr & 7) << 4);      \
            cp_async16(sb_ + 32768 + o, Ah_g + ((size_t)(b * 32 + jr)) * Cn + k0_ + ch * 8); \
            cp_async16(sb_ + 36864 + o, Al_g + ((size_t)(b * 32 + jr)) * Cn + k0_ + ch * 8); \
        }                                                                                 \
        asm volatile("cp.async.commit_group;" ::: "memory");                              \
    } while (0)

    float acc[4][4];
#pragma unroll
    for (int i = 0; i < 4; i++)
#pragma unroll
        for (int j = 0; j < 4; j++) acc[i][j] = 0.f;

    LG_LOAD(0);
    LG_LOAD(1);

    const int a_row = w * 16 + (L & 15);
    const int a_cx  = ((L >> 4) & 1) * 16;
    const int b_rb  = (L & 7) + ((L >> 4) & 1) * 8;
    const int b_cx  = ((L >> 3) & 1) * 16;

#pragma unroll 1
    for (int kt = 0; kt < 8; kt++) {
        if (kt < 7) asm volatile("cp.async.wait_group 1;" ::: "memory");
        else        asm volatile("cp.async.wait_group 0;" ::: "memory");
        __syncthreads();
        const uint32_t sb_ = sbase + (kt & 1) * LG_STAGE;
#pragma unroll
        for (int ks = 0; ks < 4; ks++) {
            uint32_t ah[4], al[4];
            uint32_t oa = (uint32_t)(a_row * 128 + ks * 32 + a_cx) ^ ((uint32_t)(a_row & 7) << 4);
            ldx4(ah, sb_ + oa);
            ldx4(al, sb_ + 16384 + oa);
            uint32_t bh[2][4], bl[2][4];
#pragma unroll
            for (int p = 0; p < 2; p++) {
                const int rn = b_rb + p * 16;
                uint32_t ob_ = (uint32_t)(rn * 128 + ks * 32 + b_cx) ^ ((uint32_t)(rn & 7) << 4);
                ldx4(bh[p], sb_ + 32768 + ob_);
                ldx4(bl[p], sb_ + 36864 + ob_);
            }
#pragma unroll
            for (int nt = 0; nt < 4; nt++) {
                const int p = nt >> 1, pi = (nt & 1) * 2;
                mma16816(acc[nt], ah, bh[p][pi], bh[p][pi + 1]);
                mma16816(acc[nt], ah, bl[p][pi], bl[p][pi + 1]);
                mma16816(acc[nt], al, bh[p][pi], bh[p][pi + 1]);
            }
        }
        if (kt + 2 < 8) { __syncthreads(); LG_LOAD(kt + 2); }
    }
#undef LG_LOAD

    const int g  = L >> 2;
    const int cq = (L & 3) * 2;
    const float* bqs = (const float*)(smem + 2 * LG_STAGE);
    const int tk0 = tokblk + w * 16 + g;
#pragma unroll
    for (int nt = 0; nt < 4; nt++) {
        const int j0 = nt * 8 + cq;
        if (nt < 2) {
            float2 v0 = make_float2((acc[nt][0] + bqs[j0]) * SCALE, (acc[nt][1] + bqs[j0 + 1]) * SCALE);
            float2 v1 = make_float2((acc[nt][2] + bqs[j0]) * SCALE, (acc[nt][3] + bqs[j0 + 1]) * SCALE);
            *(float2*)(L1 + ((size_t)b * Nn + tk0)     * 16 + j0) = v0;
            *(float2*)(L1 + ((size_t)b * Nn + tk0 + 8) * 16 + j0) = v1;
        } else {
            const int m0 = j0 - 16;
            L2[((size_t)b * 16 + m0)     * Nn + tk0]     = acc[nt][0] * SCALE;
            L2[((size_t)b * 16 + m0 + 1) * Nn + tk0]     = acc[nt][1] * SCALE;
            L2[((size_t)b * 16 + m0)     * Nn + tk0 + 8] = acc[nt][2] * SCALE;
            L2[((size_t)b * 16 + m0 + 1) * Nn + tk0 + 8] = acc[nt][3] * SCALE;
        }
    }
}

// ================= xa via mma (unchanged from R12/13) =================
#define PS_STRIDE 1040
#define XA_PS 33280
#define XA_XOFF 66560
#define XA_STAGE 16384
#define XA_SMEM (XA_XOFF + 2 * XA_STAGE)

__global__ __launch_bounds__(256)
void xa_mma(const float* __restrict__ L2, const __half* __restrict__ Xh,
            const __half* __restrict__ Xl, float* __restrict__ xa)
{
    extern __shared__ char smem[];
    const uint32_t sbase = smem_u32(smem);
    const int b  = blockIdx.y;
    const int c0 = blockIdx.x * 64;
    const int t  = threadIdx.x;
    const int L  = t & 31;
    const int w  = t >> 5;

    __half* psh = (__half*)smem;
    __half* psl = (__half*)(smem + XA_PS);
    for (int mr = w; mr < 16; mr += 8) {
        const float* row = L2 + ((size_t)b * 16 + mr) * Nn;
        float mx = -INFINITY;
#pragma unroll
        for (int i = 0; i < 32; i++) mx = fmaxf(mx, __ldg(row + L + 32 * i));
#pragma unroll
        for (int off = 16; off > 0; off >>= 1)
            mx = fmaxf(mx, __shfl_xor_sync(0xffffffffu, mx, off));
        float sum = 0.f;
#pragma unroll
        for (int i = 0; i < 32; i++) sum += __expf(__ldg(row + L + 32 * i) - mx);
#pragma unroll
        for (int off = 16; off > 0; off >>= 1)
            sum += __shfl_xor_sync(0xffffffffu, sum, off);
        const float inv = 1.0f / sum;
#pragma unroll
        for (int i = 0; i < 32; i++) {
            float e = __expf(__ldg(row + L + 32 * i) - mx) * inv;
            __half h = __float2half(e);
            psh[mr * PS_STRIDE + L + 32 * i] = h;
            psl[mr * PS_STRIDE + L + 32 * i] = __float2half(e - __half2float(h));
        }
    }
    __syncthreads();

#define XA_LOAD(I)                                                                        \
    do {                                                                                  \
        const int s_ = (I) & 1; const int k0_ = (I) * 64;                                 \
        const uint32_t xb_ = sbase + XA_XOFF + s_ * XA_STAGE;                             \
        const int row = t >> 2; const int cb = (t & 3) * 2;                               \
        const __half* gh = Xh + ((size_t)(b * Nn + k0_ + row)) * Cn + c0 + cb * 8;        \
        const __half* gl = Xl + ((size_t)(b * Nn + k0_ + row)) * Cn + c0 + cb * 8;        \
        _Pragma("unroll")                                                                 \
        for (int j = 0; j < 2; j++) {                                                     \
            uint32_t o = (uint32_t)(row * 128 + (cb + j) * 16) ^ ((uint32_t)(row & 7) << 4); \
            cp_async16(xb_ + o, gh + j * 8);                                              \
            cp_async16(xb_ + 8192 + o, gl + j * 8);                                       \
        }                                                                                 \
        asm volatile("cp.async.commit_group;" ::: "memory");                              \
    } while (0)

    float acc[4] = {0.f, 0.f, 0.f, 0.f};
    XA_LOAD(0);
    XA_LOAD(1);

    const int arow = L & 15;
    const int asel = ((L >> 4) & 1) * 16;
    const int brl  = L & 15;
    const uint32_t ph_b = sbase;
    const uint32_t pl_b = sbase + XA_PS;

#pragma unroll 1
    for (int kt = 0; kt < 16; kt++) {
        if (kt < 15) asm volatile("cp.async.wait_group 1;" ::: "memory");
        else         asm volatile("cp.async.wait_group 0;" ::: "memory");
        __syncthreads();
        const uint32_t xb_ = sbase + XA_XOFF + (kt & 1) * XA_STAGE;
#pragma unroll
        for (int ks = 0; ks < 4; ks++) {
            const int kbyte = (kt * 64 + ks * 16) * 2 + asel;
            uint32_t pa[4], pb2[4];
            ldx4(pa,  ph_b + (uint32_t)(arow * (PS_STRIDE * 2) + kbyte));
            ldx4(pb2, pl_b + (uint32_t)(arow * (PS_STRIDE * 2) + kbyte));
            const int r = ks * 16 + brl;
            uint32_t ob_ = (uint32_t)(r * 128 + w * 16) ^ ((uint32_t)(r & 7) << 4);
            uint32_t bh[2], bl2[2];
            ldx2t(bh,  xb_ + ob_);
            ldx2t(bl2, xb_ + 8192 + ob_);
            mma16816(acc, pa,  bh[0],  bh[1]);
            mma16816(acc, pa,  bl2[0], bl2[1]);
            mma16816(acc, pb2, bh[0],  bh[1]);
        }
        if (kt + 2 < 16) { __syncthreads(); XA_LOAD(kt + 2); }
    }
#undef XA_LOAD

    const int g  = L >> 2;
    const int cq = (L & 3) * 2;
    const int c  = c0 + w * 8 + cq;
    *(float2*)(xa + ((size_t)b * 16 + g)     * Cn + c) = make_float2(acc[0], acc[1]);
    *(float2*)(xa + ((size_t)b * 16 + g + 8) * Cn + c) = make_float2(acc[2], acc[3]);
}

// ================= final (unchanged from R11-13) =================
__global__ __launch_bounds__(512)
void final_kernel(const float* __restrict__ L1, const float* __restrict__ AFo,
                  const float* __restrict__ bo, float* __restrict__ out)
{
    __shared__ float4 afo4[Mn * 128];
    __shared__ float  l1s[64 * 16];
    __shared__ float4 bo4[128];
    const int b    = blockIdx.y;
    const int n0   = blockIdx.x * 64;
    const int tid  = threadIdx.x;
    const int warp = tid >> 5;
    const int lane = tid & 31;

    {
        const float4* s = (const float4*)(AFo + (size_t)b * Mn * Cn);
        for (int i = tid; i < 2048; i += 512) afo4[i] = s[i];
        const float4* sl = (const float4*)(L1 + ((size_t)b * Nn + n0) * 16);
        if (tid < 256) ((float4*)l1s)[tid] = sl[tid];
        if (tid < 128) bo4[tid] = ((const float4*)bo)[tid];
    }
    __syncthreads();

#pragma unroll 1
    for (int t = 0; t < 4; t++) {
        const int tok = warp * 4 + t;
        float lg[16];
#pragma unroll
        for (int m = 0; m < Mn; m++) lg[m] = l1s[tok * 16 + m];
        float mx = lg[0];
#pragma unroll
        for (int m = 1; m < Mn; m++) mx = fmaxf(mx, lg[m]);
        float s = 0.f;
#pragma unroll
        for (int m = 0; m < Mn; m++) { lg[m] = __expf(lg[m] - mx); s += lg[m]; }
        const float inv = 1.0f / s;

        float4* orow = (float4*)(out + ((size_t)b * Nn + n0 + tok) * Cn);
#pragma unroll 1
        for (int kc = 0; kc < 4; kc++) {
            const int cidx = kc * 32 + lane;
            float4 acc = make_float4(0.f, 0.f, 0.f, 0.f);
#pragma unroll
            for (int m = 0; m < Mn; m++) {
                float4 f = afo4[m * 128 + cidx];
                acc.x = fmaf(lg[m], f.x, acc.x);
                acc.y = fmaf(lg[m], f.y, acc.y);
                acc.z = fmaf(lg[m], f.z, acc.z);
                acc.w = fmaf(lg[m], f.w, acc.w);
            }
            float4 bb = bo4[cidx];
            acc.x = acc.x * inv + bb.x;
            acc.y = acc.y * inv + bb.y;
            acc.z = acc.z * inv + bb.z;
            acc.w = acc.w * inv + bb.w;
            orow[cidx] = acc;
        }
    }
}

// ================= launch =================
extern "C" void kernel_launch(void* const* d_in, const int* in_sizes, int n_in,
                              void* d_out, int out_size)
{
    const float* x  = (const float*)d_in[0];
    const float* Wq = (const float*)d_in[1];
    const float* bq = (const float*)d_in[2];
    const float* Wk = (const float*)d_in[3];
    const float* Wv = (const float*)d_in[5];
    const float* bv = (const float*)d_in[6];
    const float* Wo = (const float*)d_in[7];
    const float* bo = (const float*)d_in[8];
    float* out = (float*)d_out;

    float *xp, *bqA, *bvo, *v, *WqT, *WvT, *WoT, *WcT, *L1, *L2, *xa, *AFo;
    __half *xh, *xl, *aqkh, *aqkl, *WqTh, *WqTl, *WkTh, *WkTl, *Ah, *Al;
    cudaGetSymbolAddress((void**)&xp,   g_xp);
    cudaGetSymbolAddress((void**)&bqA,  g_bqA);
    cudaGetSymbolAddress((void**)&bvo,  g_bvo);
    cudaGetSymbolAddress((void**)&v,    g_v);
    cudaGetSymbolAddress((void**)&WqT,  g_WqT);
    cudaGetSymbolAddress((void**)&WvT,  g_WvT);
    cudaGetSymbolAddress((void**)&WoT,  g_WoT);
    cudaGetSymbolAddress((void**)&WcT,  g_WcT);
    cudaGetSymbolAddress((void**)&L1,   g_L1);
    cudaGetSymbolAddress((void**)&L2,   g_L2);
    cudaGetSymbolAddress((void**)&xa,   g_xa);
    cudaGetSymbolAddress((void**)&AFo,  g_AFo);
    cudaGetSymbolAddress((void**)&xh,   g_xh);
    cudaGetSymbolAddress((void**)&xl,   g_xl);
    cudaGetSymbolAddress((void**)&aqkh, g_aqkh);
    cudaGetSymbolAddress((void**)&aqkl, g_aqkl);
    cudaGetSymbolAddress((void**)&WqTh, g_WqTh);
    cudaGetSymbolAddress((void**)&WqTl, g_WqTl);
    cudaGetSymbolAddress((void**)&WkTh, g_WkTh);
    cudaGetSymbolAddress((void**)&WkTl, g_WkTl);
    cudaGetSymbolAddress((void**)&Ah,   g_Ah);
    cudaGetSymbolAddress((void**)&Al,   g_Al);

    static int attr_set = 0;
    if (!attr_set) {
        cudaFuncSetAttribute(gemm_nn,      cudaFuncAttributeMaxDynamicSharedMemorySize, GEMM_SMEM);
        cudaFuncSetAttribute(gemm_awc,     cudaFuncAttributeMaxDynamicSharedMemorySize, GEMM_SMEM);
        cudaFuncSetAttribute(gemm_aqk_mma, cudaFuncAttributeMaxDynamicSharedMemorySize, AQ_SMEM);
        cudaFuncSetAttribute(logits12_mma, cudaFuncAttributeMaxDynamicSharedMemorySize, LG_SMEM);
        cudaFuncSetAttribute(xa_mma,       cudaFuncAttributeMaxDynamicSharedMemorySize, XA_SMEM);
        attr_set = 1;
    }

    // 1. prep: transposes (+fp16), v, bvo
    prep_kernel<<<dim3(16, 16, 5), dim3(32, 8)>>>(Wq, Wk, Wv, Wo, bq, bv,
                                                  WqT, WvT, WoT, WqTh, WqTl, WkTh, WkTl, v, bvo);
    // 2. split x -> fp16 h/l + pooled xp + bqA
    split_pool_kernel<<<1024, 512>>>(x, v, xh, xl, xp, bqA);
    // 3. A (fp16 h/l) = xp@WqT + bq  AND  WcT = WvT@WoT
    gemm_awc<<<192, 256, GEMM_SMEM>>>(xp, WqT, bq, Ah, Al, WvT, WoT, WcT);
    // 4. Aq|Ak -> fp16 h/l packed via mma
    gemm_aqk_mma<<<dim3(16, 8), 256, AQ_SMEM>>>(Ah, Al, WqTh, WqTl, WkTh, WkTl, aqkh, aqkl);
    // 5-6. logits + xa (fp16 mma)
    logits12_mma<<<dim3(8, 64), 256, LG_SMEM>>>(xh, xl, aqkh, aqkl, bqA, L1, L2);
    xa_mma<<<dim3(8, 64), 256, XA_SMEM>>>(L2, xh, xl, xa);
    // 7. AFo = xa@WcT + bvo
    gemm_nn<<<dim3(8, 16), 256, GEMM_SMEM>>>(xa, WcT, WcT, bvo, AFo, AFo, 8);
    // 8. final combine
    final_kernel<<<dim3(16, 64), 512>>>(L1, AFo, bo, out);
}

// round 15
// speedup vs baseline: 1.1404x; 1.1404x over previous
#include <cuda_runtime.h>
#include <cuda_fp16.h>
#include <math.h>
#include <stdint.h>

#define Cn 512
#define Bn 64
#define Nn 1024
#define Mn 16
#define SCALE 0.04419417382415922f   // 512^-0.5

// ---------------- scratch (allocation-free) ----------------
__device__ float g_xp  [1024 * 512];
__device__ float g_bqA [1024];
__device__ float g_bvo [512];
__device__ float g_v   [512];           // Wq^T bq
__device__ float g_WqT [512 * 512];
__device__ float g_L2  [64 * 16 * 1024];
__device__ float g_L1  [64 * 1024 * 16];
__device__ float g_AFo [1024 * 512];
__device__ __half g_xh   [(size_t)64 * 1024 * 512];
__device__ __half g_aqkh [64 * 32 * 512];
__device__ __half g_aqkl [64 * 32 * 512];
__device__ __half g_WqTh [512 * 512];
__device__ __half g_WqTl [512 * 512];
__device__ __half g_WkTh [512 * 512];
__device__ __half g_WkTl [512 * 512];
__device__ __half g_Ah   [1024 * 512];
__device__ __half g_Al   [1024 * 512];
__device__ __half g_Wch  [512 * 512];   // (Wo@Wv)[n][k] fp16 hi
__device__ __half g_Wcl  [512 * 512];   // lo
__device__ __half g_xah  [1024 * 512];
__device__ __half g_xal  [1024 * 512];

__device__ __forceinline__ uint32_t smem_u32(const void* p) {
    return (uint32_t)__cvta_generic_to_shared(p);
}
__device__ __forceinline__ void cp_async16(uint32_t s, const void* g) {
    asm volatile("cp.async.cg.shared.global [%0], [%1], 16;" :: "r"(s), "l"(g));
}
__device__ __forceinline__ void ldx4(uint32_t* r, uint32_t addr) {
    asm volatile("ldmatrix.sync.aligned.m8n8.x4.shared.b16 {%0,%1,%2,%3}, [%4];"
                 : "=r"(r[0]), "=r"(r[1]), "=r"(r[2]), "=r"(r[3]) : "r"(addr));
}
__device__ __forceinline__ void ldx2t(uint32_t* r, uint32_t addr) {
    asm volatile("ldmatrix.sync.aligned.m8n8.x2.trans.shared.b16 {%0,%1}, [%2];"
                 : "=r"(r[0]), "=r"(r[1]) : "r"(addr));
}
__device__ __forceinline__ void mma16816(float* c, const uint32_t* a, uint32_t b0, uint32_t b1) {
    asm volatile(
        "mma.sync.aligned.m16n8k16.row.col.f32.f16.f16.f32 "
        "{%0,%1,%2,%3}, {%4,%5,%6,%7}, {%8,%9}, {%0,%1,%2,%3};"
        : "+f"(c[0]), "+f"(c[1]), "+f"(c[2]), "+f"(c[3])
        : "r"(a[0]), "r"(a[1]), "r"(a[2]), "r"(a[3]), "r"(b0), "r"(b1));
}

// ================= prep: WqT(+fp16), WkT(fp16), v, bvo =================
// z 0: Wq -> WqT fp32 + fp16 h/l ; z 1: Wk -> WkT fp16 h/l ; z 2: vector work
__global__ void prep_kernel(const float* __restrict__ Wq, const float* __restrict__ Wk,
                            const float* __restrict__ Wo, const float* __restrict__ bq,
                            const float* __restrict__ bv,
                            float* __restrict__ WqT, __half* __restrict__ WqTh,
                            __half* __restrict__ WqTl, __half* __restrict__ WkTh,
                            __half* __restrict__ WkTl, float* __restrict__ v,
                            float* __restrict__ bvo)
{
    const int z = blockIdx.z;
    if (z == 2) {
        const int id  = blockIdx.y * 16 + blockIdx.x;
        const int tid = threadIdx.y * 32 + threadIdx.x;
        if (id < 64) {
            // bvo[r] = Wo[r,:] . bv
            const int row  = id * 8 + (tid >> 5);
            const int lane = tid & 31;
            const float* sr = Wo + (size_t)row * Cn;
            float s = 0.f;
#pragma unroll
            for (int k = 0; k < 16; k++) s += sr[lane + 32 * k] * __ldg(&bv[lane + 32 * k]);
#pragma unroll
            for (int off = 16; off > 0; off >>= 1) s += __shfl_xor_sync(0xffffffffu, s, off);
            if (lane == 0) bvo[row] = s;
        } else if (id < 66) {
            // v[n] = sum_c Wq[c,n] * bq[c]
            const int n = (id - 64) * 256 + tid;
            float s = 0.f;
#pragma unroll 8
            for (int c = 0; c < Cn; c++) s = fmaf(__ldg(&Wq[(size_t)c * Cn + n]), __ldg(&bq[c]), s);
            v[n] = s;
        }
        return;
    }
    __shared__ float t[32][33];
    const float* s = (z == 0) ? Wq : Wk;
    const int x  = blockIdx.x * 32 + threadIdx.x;
    const int y0 = blockIdx.y * 32 + threadIdx.y;
#pragma unroll
    for (int j = 0; j < 32; j += 8)
        t[threadIdx.y + j][threadIdx.x] = s[(size_t)(y0 + j) * Cn + x];
    __syncthreads();
    const int ox  = blockIdx.y * 32 + threadIdx.x;
    const int oy0 = blockIdx.x * 32 + threadIdx.y;
#pragma unroll
    for (int j = 0; j < 32; j += 8) {
        const float val = t[threadIdx.x][threadIdx.y + j];
        const size_t di = (size_t)(oy0 + j) * Cn + ox;
        __half h = __float2half(val);
        __half l = __float2half(val - __half2float(h));
        if (z == 0) {
            WqT[di] = val;
            WqTh[di] = h; WqTl[di] = l;
        } else {
            WkTh[di] = h; WkTl[di] = l;
        }
    }
}

// ================= split x -> fp16 + pooled xp + bqA = xp.v =================
__global__ __launch_bounds__(512)
void split_pool_kernel(const float* __restrict__ x, const float* __restrict__ v,
                       __half* __restrict__ xh, float* __restrict__ xp,
                       float* __restrict__ bqA)
{
    __shared__ float red[512];
    const int bm = blockIdx.x;
    const int c  = threadIdx.x;
    const size_t ob = (size_t)bm * 64 * Cn + c;
    const float* base = x + ob;
    float s = 0.f;
#pragma unroll 4
    for (int t = 0; t < 64; t++) {
        float vv = base[(size_t)t * Cn];
        s += vv;
        xh[ob + (size_t)t * Cn] = __float2half(vv);
    }
    const float xv = s * (1.0f / 64.0f);
    xp[(size_t)bm * Cn + c] = xv;

    red[c] = xv * __ldg(&v[c]);
    __syncthreads();
    for (int st = 256; st > 32; st >>= 1) {
        if (c < st) red[c] += red[c + st];
        __syncthreads();
    }
    if (c < 32) {
        float r = red[c] + red[c + 32];
#pragma unroll
        for (int off = 16; off > 0; off >>= 1) r += __shfl_xor_sync(0xffffffffu, r, off);
        if (c == 0) bqA[bm] = r;
    }
}

// ================= fp32 GEMM machinery =================
#define XS_FLOATS (64 * 36)
#define WS_FLOATS (32 * 68)
#define STAGE_FLOATS (XS_FLOATS + WS_FLOATS)
#define GEMM_SMEM (3 * STAGE_FLOATS * 4)

#define GEMM_PROLOGUE(Xp, Wp, R0, N0)                                           \
    const int tid = threadIdx.x;                                                \
    const int tx = tid & 15, ty = tid >> 4;                                     \
    const int xlr = tid >> 2, xlk = (tid & 3) * 8;                              \
    const int wwk = tid >> 3, wwn = (tid & 7) * 8;                              \
    const float* gX = (Xp) + (size_t)((R0) + xlr) * Cn + xlk;                   \
    const float* gW = (Wp) + (size_t)wwk * Cn + (N0) + wwn;                     \
    const uint32_t sbase = smem_u32(sm);                                        \
    const uint32_t xdst = sbase + (uint32_t)(xlr * 36 + xlk) * 4u;              \
    const uint32_t wdst = sbase + (uint32_t)(XS_FLOATS + wwk * 68 + wwn) * 4u;

#define G_LOAD(ST, K0)                                                          \
    do {                                                                        \
        const uint32_t so_ = (uint32_t)(ST) * (STAGE_FLOATS * 4u);              \
        cp_async16(xdst + so_,      gX + (K0));                                 \
        cp_async16(xdst + so_ + 16, gX + (K0) + 4);                             \
        cp_async16(wdst + so_,      gW + (size_t)(K0) * Cn);                    \
        cp_async16(wdst + so_ + 16, gW + (size_t)(K0) * Cn + 4);                \
        asm volatile("cp.async.commit_group;" ::: "memory");                    \
    } while (0)

#define GEMM_MAINLOOP(acc)                                                      \
    G_LOAD(0, 0);                                                               \
    G_LOAD(1, 32);                                                              \
    _Pragma("unroll 1")                                                         \
    for (int it = 0; it < 16; it++) {                                           \
        if (it < 15) asm volatile("cp.async.wait_group 1;" ::: "memory");       \
        else         asm volatile("cp.async.wait_group 0;" ::: "memory");       \
        __syncthreads();                                                        \
        if (it + 2 < 16) G_LOAD((it + 2) % 3, (it + 2) * 32);                   \
        const float* Xst = sm + (it % 3) * STAGE_FLOATS;                        \
        const float* Wst = Xst + XS_FLOATS;                                     \
        _Pragma("unroll")                                                       \
        for (int k4 = 0; k4 < 8; k4++) {                                        \
            float aa[4][4], bb[4][4];                                           \
            _Pragma("unroll")                                                   \
            for (int i = 0; i < 4; i++) {                                       \
                float4 a = *(const float4*)(Xst + (ty * 4 + i) * 36 + k4 * 4);  \
                aa[i][0] = a.x; aa[i][1] = a.y; aa[i][2] = a.z; aa[i][3] = a.w; \
            }                                                                   \
            _Pragma("unroll")                                                   \
            for (int q = 0; q < 4; q++) {                                       \
                float4 b = *(const float4*)(Wst + (k4 * 4 + q) * 68 + tx * 4);  \
                bb[q][0] = b.x; bb[q][1] = b.y; bb[q][2] = b.z; bb[q][3] = b.w; \
            }                                                                   \
            _Pragma("unroll")                                                   \
            for (int i = 0; i < 4; i++)                                         \
                _Pragma("unroll")                                               \
                for (int j = 0; j < 4; j++)                                     \
                    _Pragma("unroll")                                           \
                    for (int q = 0; q < 4; q++)                                 \
                        acc[i][j] = fmaf(aa[i][q], bb[q][j], acc[i][j]);        \
        }                                                                       \
    }

// ================= gemm_awc: A (fp16 h/l) 128 blk + Wc = Wo@Wv (fp16 h/l) 64 blk =================
__global__ __launch_bounds__(256)
void gemm_awc(const float* __restrict__ xp, const float* __restrict__ WqT,
              const float* __restrict__ bq, __half* __restrict__ Ah,
              __half* __restrict__ Al, const float* __restrict__ Wo,
              const float* __restrict__ Wv, __half* __restrict__ Wch,
              __half* __restrict__ Wcl)
{
    extern __shared__ float sm[];
    const int isA = (int)blockIdx.x < 128;
    const float *X, *W; int r0, n0;
    if (isA) {
        const int l = blockIdx.x;
        X = xp; W = WqT;
        n0 = (l & 7) * 64; r0 = (l >> 3) * 64;
    } else {
        const int l = blockIdx.x - 128;
        X = Wo; W = Wv;   // Y[n][k] = sum_c Wo[n][c] Wv[c][k] = Wc[n][k]
        n0 = (l & 7) * 64; r0 = (l >> 3) * 64;
    }
    GEMM_PROLOGUE(X, W, r0, n0);

    float acc[4][4];
#pragma unroll
    for (int i = 0; i < 4; i++)
#pragma unroll
        for (int j = 0; j < 4; j++) acc[i][j] = 0.f;

    GEMM_MAINLOOP(acc);

    if (isA) {
        float4 bi = *(const float4*)(bq + n0 + tx * 4);
#pragma unroll
        for (int i = 0; i < 4; i++) {
            float o0 = acc[i][0] + bi.x, o1 = acc[i][1] + bi.y;
            float o2 = acc[i][2] + bi.z, o3 = acc[i][3] + bi.w;
            const size_t dst = (size_t)(r0 + ty * 4 + i) * Cn + n0 + tx * 4;
            __half h0 = __float2half(o0), h1 = __float2half(o1);
            __half h2 = __float2half(o2), h3 = __float2half(o3);
            *(__half2*)(Ah + dst)     = __halves2half2(h0, h1);
            *(__half2*)(Ah + dst + 2) = __halves2half2(h2, h3);
            *(__half2*)(Al + dst)     = __halves2half2(__float2half(o0 - __half2float(h0)),
                                                       __float2half(o1 - __half2float(h1)));
            *(__half2*)(Al + dst + 2) = __halves2half2(__float2half(o2 - __half2float(h2)),
                                                       __float2half(o3 - __half2float(h3)));
        }
    } else {
#pragma unroll
        for (int i = 0; i < 4; i++) {
            const size_t dst = (size_t)(r0 + ty * 4 + i) * Cn + n0 + tx * 4;
            __half h0 = __float2half(acc[i][0]), h1 = __float2half(acc[i][1]);
            __half h2 = __float2half(acc[i][2]), h3 = __float2half(acc[i][3]);
            *(__half2*)(Wch + dst)     = __halves2half2(h0, h1);
            *(__half2*)(Wch + dst + 2) = __halves2half2(h2, h3);
            *(__half2*)(Wcl + dst)     = __halves2half2(__float2half(acc[i][0] - __half2float(h0)),
                                                        __float2half(acc[i][1] - __half2float(h1)));
            *(__half2*)(Wcl + dst + 2) = __halves2half2(__float2half(acc[i][2] - __half2float(h2)),
                                                        __float2half(acc[i][3] - __half2float(h3)));
        }
    }
}

// ================= shared h/l-NT mma skeleton (A[r][k] h/l  x  B[n][k] h/l) =================
#define HL_STAGE 49152       // Ah 16K + Al 16K + Bh 8K + Bl 8K
#define HL_SMEM (2 * HL_STAGE)

#define HL_LOAD(I, Ahg, Alg, Bhg, Blg, ROWBLK, N0)                                        \
    do {                                                                                  \
        const int s_ = (I) & 1; const int k0_ = (I) * 64;                                 \
        const uint32_t sb_ = sbase + s_ * HL_STAGE;                                       \
        {                                                                                 \
            const int row = t >> 1; const int cb = (t & 1) * 4;                           \
            const __half* gh = (Ahg) + (size_t)((ROWBLK) + row) * Cn + k0_ + cb * 8;      \
            const __half* gl = (Alg) + (size_t)((ROWBLK) + row) * Cn + k0_ + cb * 8;      \
            _Pragma("unroll")                                                             \
            for (int j = 0; j < 4; j++) {                                                 \
                uint32_t o = (uint32_t)(row * 128 + (cb + j) * 16) ^ ((uint32_t)(row & 7) << 4); \
                cp_async16(sb_ + o, gh + j * 8);                                          \
                cp_async16(sb_ + 16384 + o, gl + j * 8);                                  \
            }                                                                             \
        }                                                                                 \
        {                                                                                 \
            const int jr = t >> 2; const int ch = (t & 3) * 2;                            \
            const __half* gh = (Bhg) + (size_t)((N0) + jr) * Cn + k0_ + ch * 8;           \
            const __half* gl = (Blg) + (size_t)((N0) + jr) * Cn + k0_ + ch * 8;           \
            _Pragma("unroll")                                                             \
            for (int j = 0; j < 2; j++) {                                                 \
                uint32_t o = (uint32_t)(jr * 128 + (ch + j) * 16) ^ ((uint32_t)(jr & 7) << 4); \
                cp_async16(sb_ + 32768 + o, gh + j * 8);                                  \
                cp_async16(sb_ + 40960 + o, gl + j * 8);                                  \
            }                                                                             \
        }                                                                                 \
        asm volatile("cp.async.commit_group;" ::: "memory");                              \
    } while (0)

#define HL_MAINLOOP(Ahg, Alg, Bhg, Blg, ROWBLK, N0)                                       \
    HL_LOAD(0, Ahg, Alg, Bhg, Blg, ROWBLK, N0);                                           \
    HL_LOAD(1, Ahg, Alg, Bhg, Blg, ROWBLK, N0);                                           \
    const int a_row = w * 16 + (L & 15);                                                  \
    const int a_cx  = ((L >> 4) & 1) * 16;                                                \
    const int b_rb  = (L & 7) + ((L >> 4) & 1) * 8;                                       \
    const int b_cx  = ((L >> 3) & 1) * 16;                                                \
    _Pragma("unroll 1")                                                                   \
    for (int kt = 0; kt < 8; kt++) {                                                      \
        if (kt < 7) asm volatile("cp.async.wait_group 1;" ::: "memory");                  \
        else        asm volatile("cp.async.wait_group 0;" ::: "memory");                  \
        __syncthreads();                                                                  \
        const uint32_t sb_ = sbase + (kt & 1) * HL_STAGE;                                 \
        _Pragma("unroll")                                                                 \
        for (int ks = 0; ks < 4; ks++) {                                                  \
            uint32_t ah[4], al[4];                                                        \
            uint32_t oa = (uint32_t)(a_row * 128 + ks * 32 + a_cx) ^ ((uint32_t)(a_row & 7) << 4); \
            ldx4(ah, sb_ + oa);                                                           \
            ldx4(al, sb_ + 16384 + oa);                                                   \
            uint32_t bh[4][4], bl[4][4];                                                  \
            _Pragma("unroll")                                                             \
            for (int p = 0; p < 4; p++) {                                                 \
                const int rn = b_rb + p * 16;                                             \
                uint32_t ob_ = (uint32_t)(rn * 128 + ks * 32 + b_cx) ^ ((uint32_t)(rn & 7) << 4); \
                ldx4(bh[p], sb_ + 32768 + ob_);                                           \
                ldx4(bl[p], sb_ + 40960 + ob_);                                           \
            }                                                                             \
            _Pragma("unroll")                                                             \
            for (int nt = 0; nt < 8; nt++) {                                              \
                const int p = nt >> 1, pi = (nt & 1) * 2;                                 \
                mma16816(acc[nt], ah, bh[p][pi], bh[p][pi + 1]);                          \
                mma16816(acc[nt], ah, bl[p][pi], bl[p][pi + 1]);                          \
                mma16816(acc[nt], al, bh[p][pi], bh[p][pi + 1]);                          \
            }                                                                             \
        }                                                                                 \
        if (kt + 2 < 8) { __syncthreads(); HL_LOAD(kt + 2, Ahg, Alg, Bhg, Blg, ROWBLK, N0); } \
    }

// ================= gemm_aqk_mma: Aq|Ak, fp16 h/l out, remapped [b][32][512] =================
__global__ __launch_bounds__(256)
void gemm_aqk_mma(const __half* __restrict__ Ahg, const __half* __restrict__ Alg,
                  const __half* __restrict__ Wqh, const __half* __restrict__ Wql,
                  const __half* __restrict__ Wkh, const __half* __restrict__ Wkl,
                  __half* __restrict__ Oh, __half* __restrict__ Ol)
{
    extern __shared__ char smem[];
    const uint32_t sbase = smem_u32(smem);
    const int isK = (int)blockIdx.x >= 8;
    const __half* Bh_g = isK ? Wkh : Wqh;
    const __half* Bl_g = isK ? Wkl : Wql;
    const int n0 = ((int)blockIdx.x & 7) * 64;
    const int rowblk = blockIdx.y * 128;
    const int t = threadIdx.x;
    const int L = t & 31;
    const int w = t >> 5;

    float acc[8][4];
#pragma unroll
    for (int i = 0; i < 8; i++)
#pragma unroll
        for (int j = 0; j < 4; j++) acc[i][j] = 0.f;

    HL_MAINLOOP(Ahg, Alg, Bh_g, Bl_g, rowblk, n0);

    const int g  = L >> 2;
    const int cq = (L & 3) * 2;
    const int joff = isK ? 16 : 0;
    const int r0v = rowblk + w * 16 + g;
    const int r1v = r0v + 8;
    const size_t d0 = ((size_t)(r0v >> 4) * 32 + (r0v & 15) + joff) * Cn + n0;
    const size_t d1 = ((size_t)(r1v >> 4) * 32 + (r1v & 15) + joff) * Cn + n0;
#pragma unroll
    for (int nt = 0; nt < 8; nt++) {
        const int col = nt * 8 + cq;
        __half h0 = __float2half(acc[nt][0]);
        __half h1 = __float2half(acc[nt][1]);
        __half h2 = __float2half(acc[nt][2]);
        __half h3 = __float2half(acc[nt][3]);
        *(__half2*)(Oh + d0 + col) = __halves2half2(h0, h1);
        *(__half2*)(Oh + d1 + col) = __halves2half2(h2, h3);
        *(__half2*)(Ol + d0 + col) = __halves2half2(__float2half(acc[nt][0] - __half2float(h0)),
                                                    __float2half(acc[nt][1] - __half2float(h1)));
        *(__half2*)(Ol + d1 + col) = __halves2half2(__float2half(acc[nt][2] - __half2float(h2)),
                                                    __float2half(acc[nt][3] - __half2float(h3)));
    }
}

// ================= gemm_afo_mma: AFo = (xah+xal)@(Wch+Wcl)^T + bvo (fp32 out) =================
__global__ __launch_bounds__(256)
void gemm_afo_mma(const __half* __restrict__ xahg, const __half* __restrict__ xalg,
                  const __half* __restrict__ Wch, const __half* __restrict__ Wcl,
                  const float* __restrict__ bvo, float* __restrict__ AFo)
{
    extern __shared__ char smem[];
    const uint32_t sbase = smem_u32(smem);
    const int n0 = blockIdx.x * 64;
    const int rowblk = blockIdx.y * 128;
    const int t = threadIdx.x;
    const int L = t & 31;
    const int w = t >> 5;

    float acc[8][4];
#pragma unroll
    for (int i = 0; i < 8; i++)
#pragma unroll
        for (int j = 0; j < 4; j++) acc[i][j] = 0.f;

    HL_MAINLOOP(xahg, xalg, Wch, Wcl, rowblk, n0);

    const int g  = L >> 2;
    const int cq = (L & 3) * 2;
    const int r0v = rowblk + w * 16 + g;
#pragma unroll
    for (int nt = 0; nt < 8; nt++) {
        const int col = n0 + nt * 8 + cq;
        const float b0 = __ldg(&bvo[col]);
        const float b1 = __ldg(&bvo[col + 1]);
        *(float2*)(AFo + (size_t)r0v * Cn + col)       = make_float2(acc[nt][0] + b0, acc[nt][1] + b1);
        *(float2*)(AFo + (size_t)(r0v + 8) * Cn + col) = make_float2(acc[nt][2] + b0, acc[nt][3] + b1);
    }
}

// ================= logits via mma: x single fp16, A h/l =================
#define LG_STAGE 24576       // xh 16K + Ah 4K + Al 4K
#define LG_SMEM (2 * LG_STAGE + 64)

__global__ __launch_bounds__(256)
void logits12_mma(const __half* __restrict__ Xh,
                  const __half* __restrict__ Ah_g, const __half* __restrict__ Al_g,
                  const float* __restrict__ bqA,
                  float* __restrict__ L1, float* __restrict__ L2)
{
    extern __shared__ char smem[];
    const uint32_t sbase = smem_u32(smem);
    const int b = blockIdx.y;
    const int tokblk = blockIdx.x * 128;
    const int t = threadIdx.x;
    const int L = t & 31;
    const int w = t >> 5;

    if (t < 16) ((float*)(smem + 2 * LG_STAGE))[t] = bqA[b * 16 + t];

#define LG_LOAD(I)                                                                        \
    do {                                                                                  \
        const int s_ = (I) & 1; const int k0_ = (I) * 64;                                 \
        const uint32_t sb_ = sbase + s_ * LG_STAGE;                                       \
        {                                                                                 \
            const int row = t >> 1; const int cb = (t & 1) * 4;                           \
            const __half* gh = Xh + ((size_t)(b * Nn + tokblk + row)) * Cn + k0_ + cb * 8;\
            _Pragma("unroll")                                                             \
            for (int j = 0; j < 4; j++) {                                                 \
                uint32_t o = (uint32_t)(row * 128 + (cb + j) * 16) ^ ((uint32_t)(row & 7) << 4); \
                cp_async16(sb_ + o, gh + j * 8);                                          \
            }                                                                             \
        }                                                                                 \
        {                                                                                 \
            const int jr = t >> 3; const int ch = t & 7;                                  \
            uint32_t o = (uint32_t)(jr * 128 + ch * 16) ^ ((uint32_t)(jr & 7) << 4);      \
            cp_async16(sb_ + 16384 + o, Ah_g + ((size_t)(b * 32 + jr)) * Cn + k0_ + ch * 8); \
            cp_async16(sb_ + 20480 + o, Al_g + ((size_t)(b * 32 + jr)) * Cn + k0_ + ch * 8); \
        }                                                                                 \
        asm volatile("cp.async.commit_group;" ::: "memory");                              \
    } while (0)

    float acc[4][4];
#pragma unroll
    for (int i = 0; i < 4; i++)
#pragma unroll
        for (int j = 0; j < 4; j++) acc[i][j] = 0.f;

    LG_LOAD(0);
    LG_LOAD(1);

    const int a_row = w * 16 + (L & 15);
    const int a_cx  = ((L >> 4) & 1) * 16;
    const int b_rb  = (L & 7) + ((L >> 4) & 1) * 8;
    const int b_cx  = ((L >> 3) & 1) * 16;

#pragma unroll 1
    for (int kt = 0; kt < 8; kt++) {
        if (kt < 7) asm volatile("cp.async.wait_group 1;" ::: "memory");
        else        asm volatile("cp.async.wait_group 0;" ::: "memory");
        __syncthreads();
        const uint32_t sb_ = sbase + (kt & 1) * LG_STAGE;
#pragma unroll
        for (int ks = 0; ks < 4; ks++) {
            uint32_t ah[4];
            uint32_t oa = (uint32_t)(a_row * 128 + ks * 32 + a_cx) ^ ((uint32_t)(a_row & 7) << 4);
            ldx4(ah, sb_ + oa);
            uint32_t bh[2][4], bl[2][4];
#pragma unroll
            for (int p = 0; p < 2; p++) {
                const int rn = b_rb + p * 16;
                uint32_t ob_ = (uint32_t)(rn * 128 + ks * 32 + b_cx) ^ ((uint32_t)(rn & 7) << 4);
                ldx4(bh[p], sb_ + 16384 + ob_);
                ldx4(bl[p], sb_ + 20480 + ob_);
            }
#pragma unroll
            for (int nt = 0; nt < 4; nt++) {
                const int p = nt >> 1, pi = (nt & 1) * 2;
                mma16816(acc[nt], ah, bh[p][pi], bh[p][pi + 1]);
                mma16816(acc[nt], ah, bl[p][pi], bl[p][pi + 1]);
            }
        }
        if (kt + 2 < 8) { __syncthreads(); LG_LOAD(kt + 2); }
    }
#undef LG_LOAD

    const int g  = L >> 2;
    const int cq = (L & 3) * 2;
    const float* bqs = (const float*)(smem + 2 * LG_STAGE);
    const int tk0 = tokblk + w * 16 + g;
#pragma unroll
    for (int nt = 0; nt < 4; nt++) {
        const int j0 = nt * 8 + cq;
        if (nt < 2) {
            float2 v0 = make_float2((acc[nt][0] + bqs[j0]) * SCALE, (acc[nt][1] + bqs[j0 + 1]) * SCALE);
            float2 v1 = make_float2((acc[nt][2] + bqs[j0]) * SCALE, (acc[nt][3] + bqs[j0 + 1]) * SCALE);
            *(float2*)(L1 + ((size_t)b * Nn + tk0)     * 16 + j0) = v0;
            *(float2*)(L1 + ((size_t)b * Nn + tk0 + 8) * 16 + j0) = v1;
        } else {
            const int m0 = j0 - 16;
            L2[((size_t)b * 16 + m0)     * Nn + tk0]     = acc[nt][0] * SCALE;
            L2[((size_t)b * 16 + m0 + 1) * Nn + tk0]     = acc[nt][1] * SCALE;
            L2[((size_t)b * 16 + m0)     * Nn + tk0 + 8] = acc[nt][2] * SCALE;
            L2[((size_t)b * 16 + m0 + 1) * Nn + tk0 + 8] = acc[nt][3] * SCALE;
        }
    }
}

// ================= xa via mma: P h/l, x single fp16; fp16 h/l out =================
#define PS_STRIDE 1040
#define XA_PS 33280
#define XA_XOFF 66560
#define XA_STAGE 8192        // xh only
#define XA_SMEM (XA_XOFF + 2 * XA_STAGE)   // 82944

__global__ __launch_bounds__(256)
void xa_mma(const float* __restrict__ L2, const __half* __restrict__ Xh,
            __half* __restrict__ xah, __half* __restrict__ xal)
{
    extern __shared__ char smem[];
    const uint32_t sbase = smem_u32(smem);
    const int b  = blockIdx.y;
    const int c0 = blockIdx.x * 64;
    const int t  = threadIdx.x;
    const int L  = t & 31;
    const int w  = t >> 5;

    __half* psh = (__half*)smem;
    __half* psl = (__half*)(smem + XA_PS);
    for (int mr = w; mr < 16; mr += 8) {
        const float* row = L2 + ((size_t)b * 16 + mr) * Nn;
        float mx = -INFINITY;
#pragma unroll
        for (int i = 0; i < 32; i++) mx = fmaxf(mx, __ldg(row + L + 32 * i));
#pragma unroll
        for (int off = 16; off > 0; off >>= 1)
            mx = fmaxf(mx, __shfl_xor_sync(0xffffffffu, mx, off));
        float sum = 0.f;
#pragma unroll
        for (int i = 0; i < 32; i++) sum += __expf(__ldg(row + L + 32 * i) - mx);
#pragma unroll
        for (int off = 16; off > 0; off >>= 1)
            sum += __shfl_xor_sync(0xffffffffu, sum, off);
        const float inv = 1.0f / sum;
#pragma unroll
        for (int i = 0; i < 32; i++) {
            float e = __expf(__ldg(row + L + 32 * i) - mx) * inv;
            __half h = __float2half(e);
            psh[mr * PS_STRIDE + L + 32 * i] = h;
            psl[mr * PS_STRIDE + L + 32 * i] = __float2half(e - __half2float(h));
        }
    }
    __syncthreads();

#define XA_LOAD(I)                                                                        \
    do {                                                                                  \
        const int s_ = (I) & 1; const int k0_ = (I) * 64;                                 \
        const uint32_t xb_ = sbase + XA_XOFF + s_ * XA_STAGE;                             \
        const int row = t >> 2; const int cb = (t & 3) * 2;                               \
        const __half* gh = Xh + ((size_t)(b * Nn + k0_ + row)) * Cn + c0 + cb * 8;        \
        _Pragma("unroll")                                                                 \
        for (int j = 0; j < 2; j++) {                                                     \
            uint32_t o = (uint32_t)(row * 128 + (cb + j) * 16) ^ ((uint32_t)(row & 7) << 4); \
            cp_async16(xb_ + o, gh + j * 8);                                              \
        }                                                                                 \
        asm volatile("cp.async.commit_group;" ::: "memory");                              \
    } while (0)

    float acc[4] = {0.f, 0.f, 0.f, 0.f};
    XA_LOAD(0);
    XA_LOAD(1);

    const int arow = L & 15;
    const int asel = ((L >> 4) & 1) * 16;
    const int brl  = L & 15;
    const uint32_t ph_b = sbase;
    const uint32_t pl_b = sbase + XA_PS;

#pragma unroll 1
    for (int kt = 0; kt < 16; kt++) {
        if (kt < 15) asm volatile("cp.async.wait_group 1;" ::: "memory");
        else         asm volatile("cp.async.wait_group 0;" ::: "memory");
        __syncthreads();
        const uint32_t xb_ = sbase + XA_XOFF + (kt & 1) * XA_STAGE;
#pragma unroll
        for (int ks = 0; ks < 4; ks++) {
            const int kbyte = (kt * 64 + ks * 16) * 2 + asel;
            uint32_t pa[4], pb2[4];
            ldx4(pa,  ph_b + (uint32_t)(arow * (PS_STRIDE * 2) + kbyte));
            ldx4(pb2, pl_b + (uint32_t)(arow * (PS_STRIDE * 2) + kbyte));
            const int r = ks * 16 + brl;
            uint32_t bh[2];
            uint32_t ob_ = (uint32_t)(r * 128 + w * 16) ^ ((uint32_t)(r & 7) << 4);
            ldx2t(bh, xb_ + ob_);
            mma16816(acc, pa,  bh[0], bh[1]);
            mma16816(acc, pb2, bh[0], bh[1]);
        }
        if (kt + 2 < 16) { __syncthreads(); XA_LOAD(kt + 2); }
    }
#undef XA_LOAD

    const int g  = L >> 2;
    const int cq = (L & 3) * 2;
    const int c  = c0 + w * 8 + cq;
    const size_t d0 = ((size_t)b * 16 + g) * Cn + c;
    const size_t d1 = ((size_t)b * 16 + g + 8) * Cn + c;
    __half h0 = __float2half(acc[0]), h1 = __float2half(acc[1]);
    __half h2 = __float2half(acc[2]), h3 = __float2half(acc[3]);
    *(__half2*)(xah + d0) = __halves2half2(h0, h1);
    *(__half2*)(xah + d1) = __halves2half2(h2, h3);
    *(__half2*)(xal + d0) = __halves2half2(__float2half(acc[0] - __half2float(h0)),
                                           __float2half(acc[1] - __half2float(h1)));
    *(__half2*)(xal + d1) = __halves2half2(__float2half(acc[2] - __half2float(h2)),
                                           __float2half(acc[3] - __half2float(h3)));
}

// ================= final (unchanged) =================
__global__ __launch_bounds__(512)
void final_kernel(const float* __restrict__ L1, const float* __restrict__ AFo,
                  const float* __restrict__ bo, float* __restrict__ out)
{
    __shared__ float4 afo4[Mn * 128];
    __shared__ float  l1s[64 * 16];
    __shared__ float4 bo4[128];
    const int b    = blockIdx.y;
    const int n0   = blockIdx.x * 64;
    const int tid  = threadIdx.x;
    const int warp = tid >> 5;
    const int lane = tid & 31;

    {
        const float4* s = (const float4*)(AFo + (size_t)b * Mn * Cn);
        for (int i = tid; i < 2048; i += 512) afo4[i] = s[i];
        const float4* sl = (const float4*)(L1 + ((size_t)b * Nn + n0) * 16);
        if (tid < 256) ((float4*)l1s)[tid] = sl[tid];
        if (tid < 128) bo4[tid] = ((const float4*)bo)[tid];
    }
    __syncthreads();

#pragma unroll 1
    for (int t = 0; t < 4; t++) {
        const int tok = warp * 4 + t;
        float lg[16];
#pragma unroll
        for (int m = 0; m < Mn; m++) lg[m] = l1s[tok * 16 + m];
        float mx = lg[0];
#pragma unroll
        for (int m = 1; m < Mn; m++) mx = fmaxf(mx, lg[m]);
        float s = 0.f;
#pragma unroll
        for (int m = 0; m < Mn; m++) { lg[m] = __expf(lg[m] - mx); s += lg[m]; }
        const float inv = 1.0f / s;

        float4* orow = (float4*)(out + ((size_t)b * Nn + n0 + tok) * Cn);
#pragma unroll 1
        for (int kc = 0; kc < 4; kc++) {
            const int cidx = kc * 32 + lane;
            float4 acc = make_float4(0.f, 0.f, 0.f, 0.f);
#pragma unroll
            for (int m = 0; m < Mn; m++) {
                float4 f = afo4[m * 128 + cidx];
                acc.x = fmaf(lg[m], f.x, acc.x);
                acc.y = fmaf(lg[m], f.y, acc.y);
                acc.z = fmaf(lg[m], f.z, acc.z);
                acc.w = fmaf(lg[m], f.w, acc.w);
            }
            float4 bb = bo4[cidx];
            acc.x = acc.x * inv + bb.x;
            acc.y = acc.y * inv + bb.y;
            acc.z = acc.z * inv + bb.z;
            acc.w = acc.w * inv + bb.w;
            orow[cidx] = acc;
        }
    }
}

// ================= launch =================
extern "C" void kernel_launch(void* const* d_in, const int* in_sizes, int n_in,
                              void* d_out, int out_size)
{
    const float* x  = (const float*)d_in[0];
    const float* Wq = (const float*)d_in[1];
    const float* bq = (const float*)d_in[2];
    const float* Wk = (const float*)d_in[3];
    const float* Wv = (const float*)d_in[5];
    const float* bv = (const float*)d_in[6];
    const float* Wo = (const float*)d_in[7];
    const float* bo = (const float*)d_in[8];
    float* out = (float*)d_out;

    float *xp, *bqA, *bvo, *v, *WqT, *L1, *L2, *AFo;
    __half *xh, *aqkh, *aqkl, *WqTh, *WqTl, *WkTh, *WkTl, *Ah, *Al, *Wch, *Wcl, *xah, *xal;
    cudaGetSymbolAddress((void**)&xp,   g_xp);
    cudaGetSymbolAddress((void**)&bqA,  g_bqA);
    cudaGetSymbolAddress((void**)&bvo,  g_bvo);
    cudaGetSymbolAddress((void**)&v,    g_v);
    cudaGetSymbolAddress((void**)&WqT,  g_WqT);
    cudaGetSymbolAddress((void**)&L1,   g_L1);
    cudaGetSymbolAddress((void**)&L2,   g_L2);
    cudaGetSymbolAddress((void**)&AFo,  g_AFo);
    cudaGetSymbolAddress((void**)&xh,   g_xh);
    cudaGetSymbolAddress((void**)&aqkh, g_aqkh);
    cudaGetSymbolAddress((void**)&aqkl, g_aqkl);
    cudaGetSymbolAddress((void**)&WqTh, g_WqTh);
    cudaGetSymbolAddress((void**)&WqTl, g_WqTl);
    cudaGetSymbolAddress((void**)&WkTh, g_WkTh);
    cudaGetSymbolAddress((void**)&WkTl, g_WkTl);
    cudaGetSymbolAddress((void**)&Ah,   g_Ah);
    cudaGetSymbolAddress((void**)&Al,   g_Al);
    cudaGetSymbolAddress((void**)&Wch,  g_Wch);
    cudaGetSymbolAddress((void**)&Wcl,  g_Wcl);
    cudaGetSymbolAddress((void**)&xah,  g_xah);
    cudaGetSymbolAddress((void**)&xal,  g_xal);

    static int attr_set = 0;
    if (!attr_set) {
        cudaFuncSetAttribute(gemm_awc,     cudaFuncAttributeMaxDynamicSharedMemorySize, GEMM_SMEM);
        cudaFuncSetAttribute(gemm_aqk_mma, cudaFuncAttributeMaxDynamicSharedMemorySize, HL_SMEM);
        cudaFuncSetAttribute(gemm_afo_mma, cudaFuncAttributeMaxDynamicSharedMemorySize, HL_SMEM);
        cudaFuncSetAttribute(logits12_mma, cudaFuncAttributeMaxDynamicSharedMemorySize, LG_SMEM);
        cudaFuncSetAttribute(xa_mma,       cudaFuncAttributeMaxDynamicSharedMemorySize, XA_SMEM);
        attr_set = 1;
    }

    // 1. prep: WqT (+fp16), WkT (fp16), v, bvo
    prep_kernel<<<dim3(16, 16, 3), dim3(32, 8)>>>(Wq, Wk, Wo, bq, bv,
                                                  WqT, WqTh, WqTl, WkTh, WkTl, v, bvo);
    // 2. split x -> fp16 + pooled xp + bqA
    split_pool_kernel<<<1024, 512>>>(x, v, xh, xp, bqA);
    // 3. A (fp16 h/l) = xp@WqT + bq  AND  Wc = Wo@Wv (fp16 h/l)
    gemm_awc<<<192, 256, GEMM_SMEM>>>(xp, WqT, bq, Ah, Al, Wo, Wv, Wch, Wcl);
    // 4. Aq|Ak via mma
    gemm_aqk_mma<<<dim3(16, 8), 256, HL_SMEM>>>(Ah, Al, WqTh, WqTl, WkTh, WkTl, aqkh, aqkl);
    // 5-6. logits + xa
    logits12_mma<<<dim3(8, 64), 256, LG_SMEM>>>(xh, aqkh, aqkl, bqA, L1, L2);
    xa_mma<<<dim3(8, 64), 256, XA_SMEM>>>(L2, xh, xah, xal);
    // 7. AFo via mma
    gemm_afo_mma<<<dim3(8, 8), 256, HL_SMEM>>>(xah, xal, Wch, Wcl, bvo, AFo);
    // 8. final combine
    final_kernel<<<dim3(16, 64), 512>>>(L1, AFo, bo, out);
}

// round 16
// speedup vs baseline: 1.2170x; 1.0671x over previous
#include <cuda_runtime.h>
#include <cuda_fp16.h>
#include <math.h>
#include <stdint.h>

#define Cn 512
#define Bn 64
#define Nn 1024
#define Mn 16
#define SCALE 0.04419417382415922f   // 512^-0.5

// ---------------- scratch (allocation-free) ----------------
__device__ float g_bqA [1024];
__device__ float g_bvo [512];
__device__ float g_v   [512];           // Wq^T bq
__device__ float g_L2  [64 * 16 * 1024];
__device__ float g_L1  [64 * 1024 * 16];
__device__ float g_AFo [1024 * 512];
__device__ __half g_xh   [(size_t)64 * 1024 * 512];
__device__ __half g_xph  [1024 * 512];
__device__ __half g_xpl  [1024 * 512];
__device__ __half g_aqkh [64 * 32 * 512];
__device__ __half g_aqkl [64 * 32 * 512];
__device__ __half g_WqTh [512 * 512];
__device__ __half g_WqTl [512 * 512];
__device__ __half g_WkTh [512 * 512];
__device__ __half g_WkTl [512 * 512];
__device__ __half g_WvTh [512 * 512];
__device__ __half g_WvTl [512 * 512];
__device__ __half g_Wqh  [512 * 512];
__device__ __half g_Wql  [512 * 512];
__device__ __half g_Woh  [512 * 512];
__device__ __half g_Wol  [512 * 512];
__device__ __half g_Ah   [1024 * 512];
__device__ __half g_Al   [1024 * 512];
__device__ __half g_Wch  [512 * 512];   // (Wo@Wv)[n][k] fp16 hi
__device__ __half g_Wcl  [512 * 512];
__device__ __half g_xah  [1024 * 512];
__device__ __half g_xal  [1024 * 512];

__device__ __forceinline__ uint32_t smem_u32(const void* p) {
    return (uint32_t)__cvta_generic_to_shared(p);
}
__device__ __forceinline__ void cp_async16(uint32_t s, const void* g) {
    asm volatile("cp.async.cg.shared.global [%0], [%1], 16;" :: "r"(s), "l"(g));
}
__device__ __forceinline__ void ldx4(uint32_t* r, uint32_t addr) {
    asm volatile("ldmatrix.sync.aligned.m8n8.x4.shared.b16 {%0,%1,%2,%3}, [%4];"
                 : "=r"(r[0]), "=r"(r[1]), "=r"(r[2]), "=r"(r[3]) : "r"(addr));
}
__device__ __forceinline__ void ldx2t(uint32_t* r, uint32_t addr) {
    asm volatile("ldmatrix.sync.aligned.m8n8.x2.trans.shared.b16 {%0,%1}, [%2];"
                 : "=r"(r[0]), "=r"(r[1]) : "r"(addr));
}
__device__ __forceinline__ void mma16816(float* c, const uint32_t* a, uint32_t b0, uint32_t b1) {
    asm volatile(
        "mma.sync.aligned.m16n8k16.row.col.f32.f16.f16.f32 "
        "{%0,%1,%2,%3}, {%4,%5,%6,%7}, {%8,%9}, {%0,%1,%2,%3};"
        : "+f"(c[0]), "+f"(c[1]), "+f"(c[2]), "+f"(c[3])
        : "r"(a[0]), "r"(a[1]), "r"(a[2]), "r"(a[3]), "r"(b0), "r"(b1));
}
__device__ __forceinline__ void split_store(__half* H, __half* Lo, size_t idx,
                                            float a, float b) {
    __half h0 = __float2half(a), h1 = __float2half(b);
    *(__half2*)(H + idx)  = __halves2half2(h0, h1);
    *(__half2*)(Lo + idx) = __halves2half2(__float2half(a - __half2float(h0)),
                                           __float2half(b - __half2float(h1)));
}

// ================= prep =================
// z0: Wq->WqT h/l ; z1: Wk->WkT h/l ; z2: Wv->WvT h/l ;
// z3: straight conversions Wq->Wqh/l, Wo->Woh/l ; z4: vector work (bvo, v)
__global__ void prep_kernel(const float* __restrict__ Wq, const float* __restrict__ Wk,
                            const float* __restrict__ Wv, const float* __restrict__ Wo,
                            const float* __restrict__ bq, const float* __restrict__ bv,
                            __half* __restrict__ WqTh, __half* __restrict__ WqTl,
                            __half* __restrict__ WkTh, __half* __restrict__ WkTl,
                            __half* __restrict__ WvTh, __half* __restrict__ WvTl,
                            __half* __restrict__ Wqh, __half* __restrict__ Wql,
                            __half* __restrict__ Woh, __half* __restrict__ Wol,
                            float* __restrict__ v, float* __restrict__ bvo)
{
    const int z = blockIdx.z;
    const int tid = threadIdx.y * 32 + threadIdx.x;
    if (z == 3) {
        const int id = blockIdx.y * 16 + blockIdx.x;     // 0..255
        const int gi = id * 256 + tid;                   // 0..65535 (float4 units)
        float4 q = ((const float4*)Wq)[gi];
        float4 o = ((const float4*)Wo)[gi];
        const size_t d = (size_t)gi * 4;
        split_store(Wqh, Wql, d,     q.x, q.y);
        split_store(Wqh, Wql, d + 2, q.z, q.w);
        split_store(Woh, Wol, d,     o.x, o.y);
        split_store(Woh, Wol, d + 2, o.z, o.w);
        return;
    }
    if (z == 4) {
        const int id = blockIdx.y * 16 + blockIdx.x;
        if (id < 64) {
            const int row  = id * 8 + (tid >> 5);
            const int lane = tid & 31;
            const float* sr = Wo + (size_t)row * Cn;
            float s = 0.f;
#pragma unroll
            for (int k = 0; k < 16; k++) s += sr[lane + 32 * k] * __ldg(&bv[lane + 32 * k]);
#pragma unroll
            for (int off = 16; off > 0; off >>= 1) s += __shfl_xor_sync(0xffffffffu, s, off);
            if (lane == 0) bvo[row] = s;
        } else if (id < 66) {
            const int n = (id - 64) * 256 + tid;
            float s = 0.f;
#pragma unroll 8
            for (int c = 0; c < Cn; c++) s = fmaf(__ldg(&Wq[(size_t)c * Cn + n]), __ldg(&bq[c]), s);
            v[n] = s;
        }
        return;
    }
    __shared__ float t[32][33];
    const float* s = (z == 0) ? Wq : (z == 1) ? Wk : Wv;
    const int x  = blockIdx.x * 32 + threadIdx.x;
    const int y0 = blockIdx.y * 32 + threadIdx.y;
#pragma unroll
    for (int j = 0; j < 32; j += 8)
        t[threadIdx.y + j][threadIdx.x] = s[(size_t)(y0 + j) * Cn + x];
    __syncthreads();
    __half *Dh, *Dl;
    if (z == 0)      { Dh = WqTh; Dl = WqTl; }
    else if (z == 1) { Dh = WkTh; Dl = WkTl; }
    else             { Dh = WvTh; Dl = WvTl; }
    const int ox  = blockIdx.y * 32 + threadIdx.x;
    const int oy0 = blockIdx.x * 32 + threadIdx.y;
#pragma unroll
    for (int j = 0; j < 32; j += 8) {
        const float val = t[threadIdx.x][threadIdx.y + j];
        const size_t di = (size_t)(oy0 + j) * Cn + ox;
        __half h = __float2half(val);
        Dh[di] = h;
        Dl[di] = __float2half(val - __half2float(h));
    }
}

// ================= split x -> fp16 + pooled xp (fp16 h/l) + bqA = xp.v =================
__global__ __launch_bounds__(512)
void split_pool_kernel(const float* __restrict__ x, const float* __restrict__ v,
                       __half* __restrict__ xh, __half* __restrict__ xph,
                       __half* __restrict__ xpl, float* __restrict__ bqA)
{
    __shared__ float red[512];
    const int bm = blockIdx.x;
    const int c  = threadIdx.x;
    const size_t ob = (size_t)bm * 64 * Cn + c;
    const float* base = x + ob;
    float s = 0.f;
#pragma unroll 4
    for (int t = 0; t < 64; t++) {
        float vv = base[(size_t)t * Cn];
        s += vv;
        xh[ob + (size_t)t * Cn] = __float2half(vv);
    }
    const float xv = s * (1.0f / 64.0f);
    {
        __half h = __float2half(xv);
        xph[(size_t)bm * Cn + c] = h;
        xpl[(size_t)bm * Cn + c] = __float2half(xv - __half2float(h));
    }

    red[c] = xv * __ldg(&v[c]);
    __syncthreads();
    for (int st = 256; st > 32; st >>= 1) {
        if (c < st) red[c] += red[c + st];
        __syncthreads();
    }
    if (c < 32) {
        float r = red[c] + red[c + 32];
#pragma unroll
        for (int off = 16; off > 0; off >>= 1) r += __shfl_xor_sync(0xffffffffu, r, off);
        if (c == 0) bqA[bm] = r;
    }
}

// ================= shared h/l-NT mma skeleton =================
#define HL_STAGE 49152       // Ah 16K + Al 16K + Bh 8K + Bl 8K
#define HL_SMEM (2 * HL_STAGE)

#define HL_LOAD(I, Ahg, Alg, Bhg, Blg, ROWBLK, N0)                                        \
    do {                                                                                  \
        const int s_ = (I) & 1; const int k0_ = (I) * 64;                                 \
        const uint32_t sb_ = sbase + s_ * HL_STAGE;                                       \
        {                                                                                 \
            const int row = t >> 1; const int cb = (t & 1) * 4;                           \
            const __half* gh = (Ahg) + (size_t)((ROWBLK) + row) * Cn + k0_ + cb * 8;      \
            const __half* gl = (Alg) + (size_t)((ROWBLK) + row) * Cn + k0_ + cb * 8;      \
            _Pragma("unroll")                                                             \
            for (int j = 0; j < 4; j++) {                                                 \
                uint32_t o = (uint32_t)(row * 128 + (cb + j) * 16) ^ ((uint32_t)(row & 7) << 4); \
                cp_async16(sb_ + o, gh + j * 8);                                          \
                cp_async16(sb_ + 16384 + o, gl + j * 8);                                  \
            }                                                                             \
        }                                                                                 \
        {                                                                                 \
            const int jr = t >> 2; const int ch = (t & 3) * 2;                            \
            const __half* gh = (Bhg) + (size_t)((N0) + jr) * Cn + k0_ + ch * 8;           \
            const __half* gl = (Blg) + (size_t)((N0) + jr) * Cn + k0_ + ch * 8;           \
            _Pragma("unroll")                                                             \
            for (int j = 0; j < 2; j++) {                                                 \
                uint32_t o = (uint32_t)(jr * 128 + (ch + j) * 16) ^ ((uint32_t)(jr & 7) << 4); \
                cp_async16(sb_ + 32768 + o, gh + j * 8);                                  \
                cp_async16(sb_ + 40960 + o, gl + j * 8);                                  \
            }                                                                             \
        }                                                                                 \
        asm volatile("cp.async.commit_group;" ::: "memory");                              \
    } while (0)

#define HL_MAINLOOP(Ahg, Alg, Bhg, Blg, ROWBLK, N0)                                       \
    HL_LOAD(0, Ahg, Alg, Bhg, Blg, ROWBLK, N0);                                           \
    HL_LOAD(1, Ahg, Alg, Bhg, Blg, ROWBLK, N0);                                           \
    const int a_row = w * 16 + (L & 15);                                                  \
    const int a_cx  = ((L >> 4) & 1) * 16;                                                \
    const int b_rb  = (L & 7) + ((L >> 4) & 1) * 8;                                       \
    const int b_cx  = ((L >> 3) & 1) * 16;                                                \
    _Pragma("unroll 1")                                                                   \
    for (int kt = 0; kt < 8; kt++) {                                                      \
        if (kt < 7) asm volatile("cp.async.wait_group 1;" ::: "memory");                  \
        else        asm volatile("cp.async.wait_group 0;" ::: "memory");                  \
        __syncthreads();                                                                  \
        const uint32_t sb_ = sbase + (kt & 1) * HL_STAGE;                                 \
        _Pragma("unroll")                                                                 \
        for (int ks = 0; ks < 4; ks++) {                                                  \
            uint32_t ah[4], al[4];                                                        \
            uint32_t oa = (uint32_t)(a_row * 128 + ks * 32 + a_cx) ^ ((uint32_t)(a_row & 7) << 4); \
            ldx4(ah, sb_ + oa);                                                           \
            ldx4(al, sb_ + 16384 + oa);                                                   \
            uint32_t bh[4][4], bl[4][4];                                                  \
            _Pragma("unroll")                                                             \
            for (int p = 0; p < 4; p++) {                                                 \
                const int rn = b_rb + p * 16;                                             \
                uint32_t ob_ = (uint32_t)(rn * 128 + ks * 32 + b_cx) ^ ((uint32_t)(rn & 7) << 4); \
                ldx4(bh[p], sb_ + 32768 + ob_);                                           \
                ldx4(bl[p], sb_ + 40960 + ob_);                                           \
            }                                                                             \
            _Pragma("unroll")                                                             \
            for (int nt = 0; nt < 8; nt++) {                                              \
                const int p = nt >> 1, pi = (nt & 1) * 2;                                 \
                mma16816(acc[nt], ah, bh[p][pi], bh[p][pi + 1]);                          \
                mma16816(acc[nt], ah, bl[p][pi], bl[p][pi + 1]);                          \
                mma16816(acc[nt], al, bh[p][pi], bh[p][pi + 1]);                          \
            }                                                                             \
        }                                                                                 \
        if (kt + 2 < 8) { __syncthreads(); HL_LOAD(kt + 2, Ahg, Alg, Bhg, Blg, ROWBLK, N0); } \
    }

// ================= gemm_a_mma: A = xp@Wq^T + bq (64 blk) AND Wc = Wo@Wv (32 blk) =================
__global__ __launch_bounds__(256)
void gemm_a_mma(const __half* __restrict__ xph, const __half* __restrict__ xpl,
                const __half* __restrict__ Wqh, const __half* __restrict__ Wql,
                const float* __restrict__ bq, __half* __restrict__ Ah,
                __half* __restrict__ Al, const __half* __restrict__ Woh,
                const __half* __restrict__ Wol, const __half* __restrict__ WvTh,
                const __half* __restrict__ WvTl, __half* __restrict__ Wch,
                __half* __restrict__ Wcl)
{
    extern __shared__ char smem[];
    const uint32_t sbase = smem_u32(smem);
    const int t = threadIdx.x;
    const int L = t & 31;
    const int w = t >> 5;
    const int isA = (int)blockIdx.x < 64;
    const __half *Ag, *Alg, *Bhg, *Blg;
    int rowblk, n0;
    if (isA) {
        Ag = xph; Alg = xpl; Bhg = Wqh; Blg = Wql;
        rowblk = ((int)blockIdx.x >> 3) * 128; n0 = ((int)blockIdx.x & 7) * 64;
    } else {
        const int l = blockIdx.x - 64;
        Ag = Woh; Alg = Wol; Bhg = WvTh; Blg = WvTl;
        rowblk = (l >> 3) * 128; n0 = (l & 7) * 64;
    }

    float acc[8][4];
#pragma unroll
    for (int i = 0; i < 8; i++)
#pragma unroll
        for (int j = 0; j < 4; j++) acc[i][j] = 0.f;

    HL_MAINLOOP(Ag, Alg, Bhg, Blg, rowblk, n0);

    const int g  = L >> 2;
    const int cq = (L & 3) * 2;
    const int r0v = rowblk + w * 16 + g;
    if (isA) {
#pragma unroll
        for (int nt = 0; nt < 8; nt++) {
            const int col = n0 + nt * 8 + cq;
            const float b0 = __ldg(&bq[col]);
            const float b1 = __ldg(&bq[col + 1]);
            split_store(Ah, Al, (size_t)r0v * Cn + col,       acc[nt][0] + b0, acc[nt][1] + b1);
            split_store(Ah, Al, (size_t)(r0v + 8) * Cn + col, acc[nt][2] + b0, acc[nt][3] + b1);
        }
    } else {
#pragma unroll
        for (int nt = 0; nt < 8; nt++) {
            const int col = n0 + nt * 8 + cq;
            split_store(Wch, Wcl, (size_t)r0v * Cn + col,       acc[nt][0], acc[nt][1]);
            split_store(Wch, Wcl, (size_t)(r0v + 8) * Cn + col, acc[nt][2], acc[nt][3]);
        }
    }
}

// ================= gemm_aqk_mma: Aq|Ak, fp16 h/l out, remapped [b][32][512] =================
__global__ __launch_bounds__(256)
void gemm_aqk_mma(const __half* __restrict__ Ahg, const __half* __restrict__ Alg,
                  const __half* __restrict__ Wqh, const __half* __restrict__ Wql,
                  const __half* __restrict__ Wkh, const __half* __restrict__ Wkl,
                  __half* __restrict__ Oh, __half* __restrict__ Ol)
{
    extern __shared__ char smem[];
    const uint32_t sbase = smem_u32(smem);
    const int isK = (int)blockIdx.x >= 8;
    const __half* Bh_g = isK ? Wkh : Wqh;
    const __half* Bl_g = isK ? Wkl : Wql;
    const int n0 = ((int)blockIdx.x & 7) * 64;
    const int rowblk = blockIdx.y * 128;
    const int t = threadIdx.x;
    const int L = t & 31;
    const int w = t >> 5;

    float acc[8][4];
#pragma unroll
    for (int i = 0; i < 8; i++)
#pragma unroll
        for (int j = 0; j < 4; j++) acc[i][j] = 0.f;

    HL_MAINLOOP(Ahg, Alg, Bh_g, Bl_g, rowblk, n0);

    const int g  = L >> 2;
    const int cq = (L & 3) * 2;
    const int joff = isK ? 16 : 0;
    const int r0v = rowblk + w * 16 + g;
    const int r1v = r0v + 8;
    const size_t d0 = ((size_t)(r0v >> 4) * 32 + (r0v & 15) + joff) * Cn + n0;
    const size_t d1 = ((size_t)(r1v >> 4) * 32 + (r1v & 15) + joff) * Cn + n0;
#pragma unroll
    for (int nt = 0; nt < 8; nt++) {
        const int col = nt * 8 + cq;
        split_store(Oh, Ol, d0 + col, acc[nt][0], acc[nt][1]);
        split_store(Oh, Ol, d1 + col, acc[nt][2], acc[nt][3]);
    }
}

// ================= gemm_afo_mma: AFo = xa@Wc^T + bvo (fp32 out) =================
__global__ __launch_bounds__(256)
void gemm_afo_mma(const __half* __restrict__ xahg, const __half* __restrict__ xalg,
                  const __half* __restrict__ Wch, const __half* __restrict__ Wcl,
                  const float* __restrict__ bvo, float* __restrict__ AFo)
{
    extern __shared__ char smem[];
    const uint32_t sbase = smem_u32(smem);
    const int n0 = blockIdx.x * 64;
    const int rowblk = blockIdx.y * 128;
    const int t = threadIdx.x;
    const int L = t & 31;
    const int w = t >> 5;

    float acc[8][4];
#pragma unroll
    for (int i = 0; i < 8; i++)
#pragma unroll
        for (int j = 0; j < 4; j++) acc[i][j] = 0.f;

    HL_MAINLOOP(xahg, xalg, Wch, Wcl, rowblk, n0);

    const int g  = L >> 2;
    const int cq = (L & 3) * 2;
    const int r0v = rowblk + w * 16 + g;
#pragma unroll
    for (int nt = 0; nt < 8; nt++) {
        const int col = n0 + nt * 8 + cq;
        const float b0 = __ldg(&bvo[col]);
        const float b1 = __ldg(&bvo[col + 1]);
        *(float2*)(AFo + (size_t)r0v * Cn + col)       = make_float2(acc[nt][0] + b0, acc[nt][1] + b1);
        *(float2*)(AFo + (size_t)(r0v + 8) * Cn + col) = make_float2(acc[nt][2] + b0, acc[nt][3] + b1);
    }
}

// ================= logits via mma: x single fp16, A h/l =================
#define LG_STAGE 24576       // xh 16K + Ah 4K + Al 4K
#define LG_SMEM (2 * LG_STAGE + 64)

__global__ __launch_bounds__(256)
void logits12_mma(const __half* __restrict__ Xh,
                  const __half* __restrict__ Ah_g, const __half* __restrict__ Al_g,
                  const float* __restrict__ bqA,
                  float* __restrict__ L1, float* __restrict__ L2)
{
    extern __shared__ char smem[];
    const uint32_t sbase = smem_u32(smem);
    const int b = blockIdx.y;
    const int tokblk = blockIdx.x * 128;
    const int t = threadIdx.x;
    const int L = t & 31;
    const int w = t >> 5;

    if (t < 16) ((float*)(smem + 2 * LG_STAGE))[t] = bqA[b * 16 + t];

#define LG_LOAD(I)                                                                        \
    do {                                                                                  \
        const int s_ = (I) & 1; const int k0_ = (I) * 64;                                 \
        const uint32_t sb_ = sbase + s_ * LG_STAGE;                                       \
        {                                                                                 \
            const int row = t >> 1; const int cb = (t & 1) * 4;                           \
            const __half* gh = Xh + ((size_t)(b * Nn + tokblk + row)) * Cn + k0_ + cb * 8;\
            _Pragma("unroll")                                                             \
            for (int j = 0; j < 4; j++) {                                                 \
                uint32_t o = (uint32_t)(row * 128 + (cb + j) * 16) ^ ((uint32_t)(row & 7) << 4); \
                cp_async16(sb_ + o, gh + j * 8);                                          \
            }                                                                             \
        }                                                                                 \
        {                                                                                 \
            const int jr = t >> 3; const int ch = t & 7;                                  \
            uint32_t o = (uint32_t)(jr * 128 + ch * 16) ^ ((uint32_t)(jr & 7) << 4);      \
            cp_async16(sb_ + 16384 + o, Ah_g + ((size_t)(b * 32 + jr)) * Cn + k0_ + ch * 8); \
            cp_async16(sb_ + 20480 + o, Al_g + ((size_t)(b * 32 + jr)) * Cn + k0_ + ch * 8); \
        }                                                                                 \
        asm volatile("cp.async.commit_group;" ::: "memory");                              \
    } while (0)

    float acc[4][4];
#pragma unroll
    for (int i = 0; i < 4; i++)
#pragma unroll
        for (int j = 0; j < 4; j++) acc[i][j] = 0.f;

    LG_LOAD(0);
    LG_LOAD(1);

    const int a_row = w * 16 + (L & 15);
    const int a_cx  = ((L >> 4) & 1) * 16;
    const int b_rb  = (L & 7) + ((L >> 4) & 1) * 8;
    const int b_cx  = ((L >> 3) & 1) * 16;

#pragma unroll 1
    for (int kt = 0; kt < 8; kt++) {
        if (kt < 7) asm volatile("cp.async.wait_group 1;" ::: "memory");
        else        asm volatile("cp.async.wait_group 0;" ::: "memory");
        __syncthreads();
        const uint32_t sb_ = sbase + (kt & 1) * LG_STAGE;
#pragma unroll
        for (int ks = 0; ks < 4; ks++) {
            uint32_t ah[4];
            uint32_t oa = (uint32_t)(a_row * 128 + ks * 32 + a_cx) ^ ((uint32_t)(a_row & 7) << 4);
            ldx4(ah, sb_ + oa);
            uint32_t bh[2][4], bl[2][4];
#pragma unroll
            for (int p = 0; p < 2; p++) {
                const int rn = b_rb + p * 16;
                uint32_t ob_ = (uint32_t)(rn * 128 + ks * 32 + b_cx) ^ ((uint32_t)(rn & 7) << 4);
                ldx4(bh[p], sb_ + 16384 + ob_);
                ldx4(bl[p], sb_ + 20480 + ob_);
            }
#pragma unroll
            for (int nt = 0; nt < 4; nt++) {
                const int p = nt >> 1, pi = (nt & 1) * 2;
                mma16816(acc[nt], ah, bh[p][pi], bh[p][pi + 1]);
                mma16816(acc[nt], ah, bl[p][pi], bl[p][pi + 1]);
            }
        }
        if (kt + 2 < 8) { __syncthreads(); LG_LOAD(kt + 2); }
    }
#undef LG_LOAD

    const int g  = L >> 2;
    const int cq = (L & 3) * 2;
    const float* bqs = (const float*)(smem + 2 * LG_STAGE);
    const int tk0 = tokblk + w * 16 + g;
#pragma unroll
    for (int nt = 0; nt < 4; nt++) {
        const int j0 = nt * 8 + cq;
        if (nt < 2) {
            float2 v0 = make_float2((acc[nt][0] + bqs[j0]) * SCALE, (acc[nt][1] + bqs[j0 + 1]) * SCALE);
            float2 v1 = make_float2((acc[nt][2] + bqs[j0]) * SCALE, (acc[nt][3] + bqs[j0 + 1]) * SCALE);
            *(float2*)(L1 + ((size_t)b * Nn + tk0)     * 16 + j0) = v0;
            *(float2*)(L1 + ((size_t)b * Nn + tk0 + 8) * 16 + j0) = v1;
        } else {
            const int m0 = j0 - 16;
            L2[((size_t)b * 16 + m0)     * Nn + tk0]     = acc[nt][0] * SCALE;
            L2[((size_t)b * 16 + m0 + 1) * Nn + tk0]     = acc[nt][1] * SCALE;
            L2[((size_t)b * 16 + m0)     * Nn + tk0 + 8] = acc[nt][2] * SCALE;
            L2[((size_t)b * 16 + m0 + 1) * Nn + tk0 + 8] = acc[nt][3] * SCALE;
        }
    }
}

// ================= xa via mma: P h/l, x single fp16; fp16 h/l out =================
#define PS_STRIDE 1040
#define XA_PS 33280
#define XA_XOFF 66560
#define XA_STAGE 8192
#define XA_SMEM (XA_XOFF + 2 * XA_STAGE)

__global__ __launch_bounds__(256)
void xa_mma(const float* __restrict__ L2, const __half* __restrict__ Xh,
            __half* __restrict__ xah, __half* __restrict__ xal)
{
    extern __shared__ char smem[];
    const uint32_t sbase = smem_u32(smem);
    const int b  = blockIdx.y;
    const int c0 = blockIdx.x * 64;
    const int t  = threadIdx.x;
    const int L  = t & 31;
    const int w  = t >> 5;

    __half* psh = (__half*)smem;
    __half* psl = (__half*)(smem + XA_PS);
    for (int mr = w; mr < 16; mr += 8) {
        const float* row = L2 + ((size_t)b * 16 + mr) * Nn;
        float mx = -INFINITY;
#pragma unroll
        for (int i = 0; i < 32; i++) mx = fmaxf(mx, __ldg(row + L + 32 * i));
#pragma unroll
        for (int off = 16; off > 0; off >>= 1)
            mx = fmaxf(mx, __shfl_xor_sync(0xffffffffu, mx, off));
        float sum = 0.f;
#pragma unroll
        for (int i = 0; i < 32; i++) sum += __expf(__ldg(row + L + 32 * i) - mx);
#pragma unroll
        for (int off = 16; off > 0; off >>= 1)
            sum += __shfl_xor_sync(0xffffffffu, sum, off);
        const float inv = 1.0f / sum;
#pragma unroll
        for (int i = 0; i < 32; i++) {
            float e = __expf(__ldg(row + L + 32 * i) - mx) * inv;
            __half h = __float2half(e);
            psh[mr * PS_STRIDE + L + 32 * i] = h;
            psl[mr * PS_STRIDE + L + 32 * i] = __float2half(e - __half2float(h));
        }
    }
    __syncthreads();

#define XA_LOAD(I)                                                                        \
    do {                                                                                  \
        const int s_ = (I) & 1; const int k0_ = (I) * 64;                                 \
        const uint32_t xb_ = sbase + XA_XOFF + s_ * XA_STAGE;                             \
        const int row = t >> 2; const int cb = (t & 3) * 2;                               \
        const __half* gh = Xh + ((size_t)(b * Nn + k0_ + row)) * Cn + c0 + cb * 8;        \
        _Pragma("unroll")                                                                 \
        for (int j = 0; j < 2; j++) {                                                     \
            uint32_t o = (uint32_t)(row * 128 + (cb + j) * 16) ^ ((uint32_t)(row & 7) << 4); \
            cp_async16(xb_ + o, gh + j * 8);                                              \
        }                                                                                 \
        asm volatile("cp.async.commit_group;" ::: "memory");                              \
    } while (0)

    float acc[4] = {0.f, 0.f, 0.f, 0.f};
    XA_LOAD(0);
    XA_LOAD(1);

    const int arow = L & 15;
    const int asel = ((L >> 4) & 1) * 16;
    const int brl  = L & 15;
    const uint32_t ph_b = sbase;
    const uint32_t pl_b = sbase + XA_PS;

#pragma unroll 1
    for (int kt = 0; kt < 16; kt++) {
        if (kt < 15) asm volatile("cp.async.wait_group 1;" ::: "memory");
        else         asm volatile("cp.async.wait_group 0;" ::: "memory");
        __syncthreads();
        const uint32_t xb_ = sbase + XA_XOFF + (kt & 1) * XA_STAGE;
#pragma unroll
        for (int ks = 0; ks < 4; ks++) {
            const int kbyte = (kt * 64 + ks * 16) * 2 + asel;
            uint32_t pa[4], pb2[4];
            ldx4(pa,  ph_b + (uint32_t)(arow * (PS_STRIDE * 2) + kbyte));
            ldx4(pb2, pl_b + (uint32_t)(arow * (PS_STRIDE * 2) + kbyte));
            const int r = ks * 16 + brl;
            uint32_t bh[2];
            uint32_t ob_ = (uint32_t)(r * 128 + w * 16) ^ ((uint32_t)(r & 7) << 4);
            ldx2t(bh, xb_ + ob_);
            mma16816(acc, pa,  bh[0], bh[1]);
            mma16816(acc, pb2, bh[0], bh[1]);
        }
        if (kt + 2 < 16) { __syncthreads(); XA_LOAD(kt + 2); }
    }
#undef XA_LOAD

    const int g  = L >> 2;
    const int cq = (L & 3) * 2;
    const int c  = c0 + w * 8 + cq;
    split_store(xah, xal, ((size_t)b * 16 + g) * Cn + c,     acc[0], acc[1]);
    split_store(xah, xal, ((size_t)b * 16 + g + 8) * Cn + c, acc[2], acc[3]);
}

// ================= final (unchanged) =================
__global__ __launch_bounds__(512)
void final_kernel(const float* __restrict__ L1, const float* __restrict__ AFo,
                  const float* __restrict__ bo, float* __restrict__ out)
{
    __shared__ float4 afo4[Mn * 128];
    __shared__ float  l1s[64 * 16];
    __shared__ float4 bo4[128];
    const int b    = blockIdx.y;
    const int n0   = blockIdx.x * 64;
    const int tid  = threadIdx.x;
    const int warp = tid >> 5;
    const int lane = tid & 31;

    {
        const float4* s = (const float4*)(AFo + (size_t)b * Mn * Cn);
        for (int i = tid; i < 2048; i += 512) afo4[i] = s[i];
        const float4* sl = (const float4*)(L1 + ((size_t)b * Nn + n0) * 16);
        if (tid < 256) ((float4*)l1s)[tid] = sl[tid];
        if (tid < 128) bo4[tid] = ((const float4*)bo)[tid];
    }
    __syncthreads();

#pragma unroll 1
    for (int t = 0; t < 4; t++) {
        const int tok = warp * 4 + t;
        float lg[16];
#pragma unroll
        for (int m = 0; m < Mn; m++) lg[m] = l1s[tok * 16 + m];
        float mx = lg[0];
#pragma unroll
        for (int m = 1; m < Mn; m++) mx = fmaxf(mx, lg[m]);
        float s = 0.f;
#pragma unroll
        for (int m = 0; m < Mn; m++) { lg[m] = __expf(lg[m] - mx); s += lg[m]; }
        const float inv = 1.0f / s;

        float4* orow = (float4*)(out + ((size_t)b * Nn + n0 + tok) * Cn);
#pragma unroll 1
        for (int kc = 0; kc < 4; kc++) {
            const int cidx = kc * 32 + lane;
            float4 acc = make_float4(0.f, 0.f, 0.f, 0.f);
#pragma unroll
            for (int m = 0; m < Mn; m++) {
                float4 f = afo4[m * 128 + cidx];
                acc.x = fmaf(lg[m], f.x, acc.x);
                acc.y = fmaf(lg[m], f.y, acc.y);
                acc.z = fmaf(lg[m], f.z, acc.z);
                acc.w = fmaf(lg[m], f.w, acc.w);
            }
            float4 bb = bo4[cidx];
            acc.x = acc.x * inv + bb.x;
            acc.y = acc.y * inv + bb.y;
            acc.z = acc.z * inv + bb.z;
            acc.w = acc.w * inv + bb.w;
            orow[cidx] = acc;
        }
    }
}

// ================= launch =================
extern "C" void kernel_launch(void* const* d_in, const int* in_sizes, int n_in,
                              void* d_out, int out_size)
{
    const float* x  = (const float*)d_in[0];
    const float* Wq = (const float*)d_in[1];
    const float* bq = (const float*)d_in[2];
    const float* Wk = (const float*)d_in[3];
    const float* Wv = (const float*)d_in[5];
    const float* bv = (const float*)d_in[6];
    const float* Wo = (const float*)d_in[7];
    const float* bo = (const float*)d_in[8];
    float* out = (float*)d_out;

    float *bqA, *bvo, *v, *L1, *L2, *AFo;
    __half *xh, *xph, *xpl, *aqkh, *aqkl;
    __half *WqTh, *WqTl, *WkTh, *WkTl, *WvTh, *WvTl, *Wqh, *Wql, *Woh, *Wol;
    __half *Ah, *Al, *Wch, *Wcl, *xah, *xal;
    cudaGetSymbolAddress((void**)&bqA,  g_bqA);
    cudaGetSymbolAddress((void**)&bvo,  g_bvo);
    cudaGetSymbolAddress((void**)&v,    g_v);
    cudaGetSymbolAddress((void**)&L1,   g_L1);
    cudaGetSymbolAddress((void**)&L2,   g_L2);
    cudaGetSymbolAddress((void**)&AFo,  g_AFo);
    cudaGetSymbolAddress((void**)&xh,   g_xh);
    cudaGetSymbolAddress((void**)&xph,  g_xph);
    cudaGetSymbolAddress((void**)&xpl,  g_xpl);
    cudaGetSymbolAddress((void**)&aqkh, g_aqkh);
    cudaGetSymbolAddress((void**)&aqkl, g_aqkl);
    cudaGetSymbolAddress((void**)&WqTh, g_WqTh);
    cudaGetSymbolAddress((void**)&WqTl, g_WqTl);
    cudaGetSymbolAddress((void**)&WkTh, g_WkTh);
    cudaGetSymbolAddress((void**)&WkTl, g_WkTl);
    cudaGetSymbolAddress((void**)&WvTh, g_WvTh);
    cudaGetSymbolAddress((void**)&WvTl, g_WvTl);
    cudaGetSymbolAddress((void**)&Wqh,  g_Wqh);
    cudaGetSymbolAddress((void**)&Wql,  g_Wql);
    cudaGetSymbolAddress((void**)&Woh,  g_Woh);
    cudaGetSymbolAddress((void**)&Wol,  g_Wol);
    cudaGetSymbolAddress((void**)&Ah,   g_Ah);
    cudaGetSymbolAddress((void**)&Al,   g_Al);
    cudaGetSymbolAddress((void**)&Wch,  g_Wch);
    cudaGetSymbolAddress((void**)&Wcl,  g_Wcl);
    cudaGetSymbolAddress((void**)&xah,  g_xah);
    cudaGetSymbolAddress((void**)&xal,  g_xal);

    static int attr_set = 0;
    if (!attr_set) {
        cudaFuncSetAttribute(gemm_a_mma,   cudaFuncAttributeMaxDynamicSharedMemorySize, HL_SMEM);
        cudaFuncSetAttribute(gemm_aqk_mma, cudaFuncAttributeMaxDynamicSharedMemorySize, HL_SMEM);
        cudaFuncSetAttribute(gemm_afo_mma, cudaFuncAttributeMaxDynamicSharedMemorySize, HL_SMEM);
        cudaFuncSetAttribute(logits12_mma, cudaFuncAttributeMaxDynamicSharedMemorySize, LG_SMEM);
        cudaFuncSetAttribute(xa_mma,       cudaFuncAttributeMaxDynamicSharedMemorySize, XA_SMEM);
        attr_set = 1;
    }

    // 1. prep: W transposes + conversions + v + bvo
    prep_kernel<<<dim3(16, 16, 5), dim3(32, 8)>>>(Wq, Wk, Wv, Wo, bq, bv,
                                                  WqTh, WqTl, WkTh, WkTl, WvTh, WvTl,
                                                  Wqh, Wql, Woh, Wol, v, bvo);
    // 2. split x -> fp16 + pooled xp (h/l) + bqA
    split_pool_kernel<<<1024, 512>>>(x, v, xh, xph, xpl, bqA);
    // 3. A = xp@Wq^T + bq AND Wc = Wo@Wv (both mma, fp16 h/l out)
    gemm_a_mma<<<96, 256, HL_SMEM>>>(xph, xpl, Wqh, Wql, bq, Ah, Al,
                                     Woh, Wol, WvTh, WvTl, Wch, Wcl);
    // 4. Aq|Ak via mma
    gemm_aqk_mma<<<dim3(16, 8), 256, HL_SMEM>>>(Ah, Al, WqTh, WqTl, WkTh, WkTl, aqkh, aqkl);
    // 5-6. logits + xa
    logits12_mma<<<dim3(8, 64), 256, LG_SMEM>>>(xh, aqkh, aqkl, bqA, L1, L2);
    xa_mma<<<dim3(8, 64), 256, XA_SMEM>>>(L2, xh, xah, xal);
    // 7. AFo via mma
    gemm_afo_mma<<<dim3(8, 8), 256, HL_SMEM>>>(xah, xal, Wch, Wcl, bvo, AFo);
    // 8. final combine
    final_kernel<<<dim3(16, 64), 512>>>(L1, AFo, bo, out);
}